// round 4
// baseline (speedup 1.0000x reference)
#include <cuda_runtime.h>

#define CDIV(a,b) (((a)+(b)-1)/(b))

static const int NMAX = 50000;

// Scratch (device globals — no allocation allowed)
__device__ __align__(16) float g_xw  [(size_t)NMAX*242];
__device__ __align__(16) float g_acc3[(size_t)NMAX*242];
__device__ __align__(16) float g_h0  [(size_t)NMAX*64];
__device__ __align__(16) float g_h1  [(size_t)NMAX*64];
__device__ __align__(16) float g_as  [NMAX*8];
__device__ __align__(16) float g_ad  [NMAX*8];
__device__ __align__(16) float g_es  [NMAX*8];   // exp(self-loop logit)
__device__ __align__(16) float g_den [NMAX*8];

__device__ __forceinline__ float lrelu(float x){ return x > 0.f ? x : 0.2f*x; }

// ---------------- GEMM: O[N,K] = A[N,F] @ W[F,K], K even ----------------
__global__ void k_gemm(const float* __restrict__ A, const float* __restrict__ W,
                       float* __restrict__ O, int N, int F, int K){
  int K2 = K >> 1;
  long long tid = (long long)blockIdx.x*blockDim.x + threadIdx.x;
  long long total = (long long)CDIV(N,4)*K2;
  if (tid >= total) return;
  int kk = (int)(tid % K2);
  int n0 = (int)(tid / K2) * 4;
  const float2* W2 = (const float2*)W;
  if (n0 + 4 <= N){
    const float* r0 = A + (size_t)n0*F;
    const float* r1 = r0 + F;
    const float* r2 = r1 + F;
    const float* r3 = r2 + F;
    float a0=0,c0=0,a1=0,c1=0,a2=0,c2=0,a3=0,c3=0;
    for (int f=0; f<F; ++f){
      float2 w = W2[(size_t)f*K2 + kk];
      float x0=r0[f], x1=r1[f], x2=r2[f], x3=r3[f];
      a0 = fmaf(x0,w.x,a0); c0 = fmaf(x0,w.y,c0);
      a1 = fmaf(x1,w.x,a1); c1 = fmaf(x1,w.y,c1);
      a2 = fmaf(x2,w.x,a2); c2 = fmaf(x2,w.y,c2);
      a3 = fmaf(x3,w.x,a3); c3 = fmaf(x3,w.y,c3);
    }
    O[(size_t)(n0+0)*K + 2*kk] = a0; O[(size_t)(n0+0)*K + 2*kk+1] = c0;
    O[(size_t)(n0+1)*K + 2*kk] = a1; O[(size_t)(n0+1)*K + 2*kk+1] = c1;
    O[(size_t)(n0+2)*K + 2*kk] = a2; O[(size_t)(n0+2)*K + 2*kk+1] = c2;
    O[(size_t)(n0+3)*K + 2*kk] = a3; O[(size_t)(n0+3)*K + 2*kk+1] = c3;
  } else {
    for (int r=0; r<4; ++r){
      int n = n0 + r;
      if (n >= N) break;
      float s0=0, s1=0;
      for (int f=0; f<F; ++f){
        float2 w = W2[(size_t)f*K2 + kk];
        float x = A[(size_t)n*F + f];
        s0 = fmaf(x,w.x,s0); s1 = fmaf(x,w.y,s1);
      }
      O[(size_t)n*K + 2*kk] = s0; O[(size_t)n*K + 2*kk+1] = s1;
    }
  }
}

// -------- per-(node,head) logits; es = exp(self-loop e); den init = es --------
__global__ void k_node_prep(const float* __restrict__ xw, const float* __restrict__ asrc,
                            const float* __restrict__ adst, int N, int H, int C,
                            float* __restrict__ as, float* __restrict__ ad,
                            float* __restrict__ es, float* __restrict__ den){
  int t = blockIdx.x*blockDim.x + threadIdx.x;
  if (t >= N*H) return;
  int n = t / H, h = t - n*H;
  const float* row = xw + (size_t)n*H*C + (size_t)h*C;
  float s=0.f, d=0.f;
  for (int c=0; c<C; ++c){ float v = row[c]; s = fmaf(v, asrc[h*C+c], s); d = fmaf(v, adst[h*C+c], d); }
  as[t]=s; ad[t]=d;
  float e = __expf(lrelu(s+d));
  es[t]=e; den[t]=e;
}

// warp-per-node version for H==1, large C
__global__ void k_node_prep_w(const float* __restrict__ xw, const float* __restrict__ asrc,
                              const float* __restrict__ adst, int N, int C,
                              float* __restrict__ as, float* __restrict__ ad,
                              float* __restrict__ es, float* __restrict__ den){
  int w = (blockIdx.x*blockDim.x + threadIdx.x) >> 5;
  int lane = threadIdx.x & 31;
  if (w >= N) return;
  const float* row = xw + (size_t)w*C;
  float s=0.f, d=0.f;
  for (int c=lane; c<C; c+=32){ float v = row[c]; s = fmaf(v, asrc[c], s); d = fmaf(v, adst[c], d); }
  for (int o=16; o; o>>=1){ s += __shfl_xor_sync(0xffffffffu, s, o); d += __shfl_xor_sync(0xffffffffu, d, o); }
  if (lane == 0){ as[w]=s; ad[w]=d; float e = __expf(lrelu(s+d)); es[w]=e; den[w]=e; }
}

// -------- edge sweep 1: denominator accumulation --------
__global__ void k_edge_den(const int* __restrict__ src, const int* __restrict__ dst, int E,
                           const float* __restrict__ as, const float* __restrict__ ad,
                           float* __restrict__ den, int H){
  int t = blockIdx.x*blockDim.x + threadIdx.x;
  if (t >= E) return;
  int s = src[t], d = dst[t];
  #pragma unroll 8
  for (int h=0; h<H; ++h){
    float e = lrelu(as[s*H+h] + ad[d*H+h]);
    atomicAdd(&den[d*H+h], __expf(e));
  }
}

__global__ void k_node_rden(float* __restrict__ den, int NH){
  int t = blockIdx.x*blockDim.x + threadIdx.x;
  if (t >= NH) return;
  den[t] = 1.f / (den[t] + 1e-16f);
}

// -------- self-loop message (initializes accumulator) --------
__global__ void k_node_self(const float* __restrict__ xw, const float* __restrict__ es,
                            const float* __restrict__ rden,
                            float* __restrict__ acc, int N, int H, int C){
  long long t = (long long)blockIdx.x*blockDim.x + threadIdx.x;
  int F = H*C;
  if (t >= (long long)N*F) return;
  int n = (int)(t / F); int j = (int)(t - (long long)n*F); int h = j / C;
  float w = es[n*H+h] * rden[n*H+h];
  acc[t] = w * xw[t];
}

// -------- edge sweep 2 (H=8, C=8, F=64): 2 edges per warp, v4 reds --------
__global__ void k_edge_msg8(const int* __restrict__ src, const int* __restrict__ dst, int E,
                            const float* __restrict__ as, const float* __restrict__ ad,
                            const float* __restrict__ rden,
                            const float* __restrict__ xw, float* __restrict__ acc){
  int gw = (int)(((long long)blockIdx.x*blockDim.x + threadIdx.x) >> 5);
  int lane = threadIdx.x & 31;
  int half = lane >> 4;        // which of 2 edges
  int sub  = lane & 15;        // 0..15
  int e = gw*2 + half;
  if (e >= E) return;
  int s = src[e], d = dst[e];
  int j = sub*4;               // 0..60, 4 consecutive channels
  int h = j >> 3;              // head index
  float t = as[s*8+h] + ad[d*8+h];
  float a = __expf(lrelu(t)) * rden[d*8+h];
  float4 v = *(const float4*)(xw + (size_t)s*64 + j);
  float* p = acc + (size_t)d*64 + j;
  asm volatile("red.global.add.v4.f32 [%0], {%1,%2,%3,%4};"
               :: "l"(p), "f"(a*v.x), "f"(a*v.y), "f"(a*v.z), "f"(a*v.w) : "memory");
}

// -------- edge sweep 2 (H=1, C even): warp per edge, v2 reds --------
__global__ void k_edge_msg1(const int* __restrict__ src, const int* __restrict__ dst, int E,
                            const float* __restrict__ as, const float* __restrict__ ad,
                            const float* __restrict__ rden,
                            const float* __restrict__ xw, float* __restrict__ acc, int C){
  int w = (int)(((long long)blockIdx.x*blockDim.x + threadIdx.x) >> 5);
  int lane = threadIdx.x & 31;
  if (w >= E) return;
  int s = src[w], d = dst[w];
  float a = __expf(lrelu(as[s] + ad[d])) * rden[d];
  const float2* xs = (const float2*)(xw + (size_t)s*C);
  float* od = acc + (size_t)d*C;
  int C2 = C >> 1;
  for (int j = lane; j < C2; j += 32){
    float2 v = xs[j];
    asm volatile("red.global.add.v2.f32 [%0], {%1,%2};"
                 :: "l"(od + 2*j), "f"(a*v.x), "f"(a*v.y) : "memory");
  }
}

// -------- finalize layers 1/2: relu(acc + b) --------
__global__ void k_fin12(float* __restrict__ acc, const float* __restrict__ b, int N, int F){
  long long t = (long long)blockIdx.x*blockDim.x + threadIdx.x;
  if (t >= (long long)N*F) return;
  int j = (int)(t % F);
  acc[t] = fmaxf(acc[t] + b[j], 0.f);
}

// -------- finalize layer 3: relu(acc + b), pairwise softmax --------
__global__ void k_fin3(const float* __restrict__ acc, const float* __restrict__ b,
                       float* __restrict__ out, int N, int K){
  int P = K >> 1;
  long long t = (long long)blockIdx.x*blockDim.x + threadIdx.x;
  if (t >= (long long)N*P) return;
  int n = (int)(t / P); int i = (int)(t - (long long)n*P);
  size_t base = (size_t)n*K + 2*i;
  float v0 = fmaxf(acc[base]   + b[2*i],   0.f);
  float v1 = fmaxf(acc[base+1] + b[2*i+1], 0.f);
  float m = fmaxf(v0, v1);
  float e0 = __expf(v0 - m), e1 = __expf(v1 - m);
  float inv = 1.f / (e0 + e1);
  out[base]   = e0 * inv;
  out[base+1] = e1 * inv;
}

// ---------------- host side ----------------
struct Scratch {
  float *xw, *acc3, *h0, *h1, *as, *ad, *es, *den;
};

static void gat_layer(const float* hin, int Fin, int K, int H, int C,
                      const float* W, const float* asrc, const float* adst, const float* bias,
                      int N, int E, const int* src, const int* dst,
                      const Scratch& S, float* acc, float* final_out){
  const int B = 256;
  long long gth = (long long)CDIV(N,4)*(K/2);
  k_gemm<<<(unsigned)CDIV(gth,B), B>>>(hin, W, S.xw, N, Fin, K);
  if (H > 1) k_node_prep<<<CDIV(N*H,B), B>>>(S.xw, asrc, adst, N, H, C, S.as, S.ad, S.es, S.den);
  else       k_node_prep_w<<<CDIV(N*32,B), B>>>(S.xw, asrc, adst, N, C, S.as, S.ad, S.es, S.den);
  k_edge_den<<<CDIV(E,B), B>>>(src, dst, E, S.as, S.ad, S.den, H);
  k_node_rden<<<CDIV(N*H,B), B>>>(S.den, N*H);
  int F = H*C;
  k_node_self<<<(unsigned)CDIV((long long)N*F,B), B>>>(S.xw, S.es, S.den, acc, N, H, C);
  if (H == 8 && C == 8)
    k_edge_msg8<<<(unsigned)CDIV((long long)CDIV(E,2)*32,B), B>>>(src, dst, E, S.as, S.ad, S.den, S.xw, acc);
  else
    k_edge_msg1<<<(unsigned)CDIV((long long)E*32,B), B>>>(src, dst, E, S.as, S.ad, S.den, S.xw, acc, C);
  if (final_out) k_fin3<<<(unsigned)CDIV((long long)N*(K/2),B), B>>>(acc, bias, final_out, N, K);
  else           k_fin12<<<(unsigned)CDIV((long long)N*F,B), B>>>(acc, bias, N, F);
}

extern "C" void kernel_launch(void* const* d_in, const int* in_sizes, int n_in,
                              void* d_out, int out_size){
  const float* x  = (const float*)d_in[0];
  const int*   ei = (const int*)d_in[1];          // int32! (harness dtype)
  const float *W1=(const float*)d_in[2],  *a1s=(const float*)d_in[3],  *a1d=(const float*)d_in[4],  *b1=(const float*)d_in[5];
  const float *W2=(const float*)d_in[6],  *a2s=(const float*)d_in[7],  *a2d=(const float*)d_in[8],  *b2=(const float*)d_in[9];
  const float *W3=(const float*)d_in[10], *a3s=(const float*)d_in[11], *a3d=(const float*)d_in[12], *b3=(const float*)d_in[13];
  int N = in_sizes[0] / 128;
  int E = in_sizes[1] / 2;
  const int* src = ei;
  const int* dst = ei + E;

  Scratch S;
  cudaGetSymbolAddress((void**)&S.xw,   g_xw);
  cudaGetSymbolAddress((void**)&S.acc3, g_acc3);
  cudaGetSymbolAddress((void**)&S.h0,   g_h0);
  cudaGetSymbolAddress((void**)&S.h1,   g_h1);
  cudaGetSymbolAddress((void**)&S.as,   g_as);
  cudaGetSymbolAddress((void**)&S.ad,   g_ad);
  cudaGetSymbolAddress((void**)&S.es,   g_es);
  cudaGetSymbolAddress((void**)&S.den,  g_den);

  // Layer 1: 128 -> 64, H=8, C=8, concat
  gat_layer(x,    128, 64,  8, 8,   W1, a1s, a1d, b1, N, E, src, dst, S, S.h0, nullptr);
  // Layer 2: 64 -> 64, H=8, C=8, concat
  gat_layer(S.h0, 64,  64,  8, 8,   W2, a2s, a2d, b2, N, E, src, dst, S, S.h1, nullptr);
  // Layer 3: 64 -> 242, H=1, C=242, mean (=identity), then pairwise softmax
  gat_layer(S.h1, 64,  242, 1, 242, W3, a3s, a3d, b3, N, E, src, dst, S, S.acc3, (float*)d_out);
}

// round 5
// speedup vs baseline: 1.6512x; 1.6512x over previous
#include <cuda_runtime.h>

#define CDIV(a,b) (((a)+(b)-1)/(b))

static const int NMAX = 50000;
static const int EMAX = 800000;

// Scratch (device globals — no allocation allowed)
__device__ __align__(16) float g_xw  [(size_t)NMAX*242];
__device__ __align__(16) float g_h0  [(size_t)NMAX*64];
__device__ __align__(16) float g_h1  [(size_t)NMAX*64];
__device__ __align__(16) float g_as  [NMAX*8];
__device__ __align__(16) float g_ad  [NMAX*8];
__device__ int g_deg   [NMAX];
__device__ int g_rowptr[NMAX+1];
__device__ int g_cursor[NMAX];
__device__ int g_esrc  [EMAX];

__device__ __forceinline__ float lrelu(float x){ return x > 0.f ? x : 0.2f*x; }

// ---------------- CSR build ----------------
__global__ void k_hist(const int* __restrict__ dst, int E, int* __restrict__ deg){
  int t = blockIdx.x*blockDim.x + threadIdx.x;
  if (t < E) atomicAdd(&deg[dst[t]], 1);
}

// single-block exclusive scan over N elements (N ~ 50K)
__global__ void k_scan(const int* __restrict__ deg, int* __restrict__ rowptr,
                       int* __restrict__ cursor, int N){
  __shared__ int partial[1024];
  int tid = threadIdx.x;
  int chunk = CDIV(N, 1024);
  int lo = tid*chunk, hi = min(lo+chunk, N);
  int s = 0;
  for (int i = lo; i < hi; ++i) s += deg[i];
  partial[tid] = s;
  __syncthreads();
  for (int off = 1; off < 1024; off <<= 1){
    int v = (tid >= off) ? partial[tid-off] : 0;
    __syncthreads();
    partial[tid] += v;
    __syncthreads();
  }
  int run = partial[tid] - s;   // exclusive base for this chunk
  for (int i = lo; i < hi; ++i){
    rowptr[i] = run; cursor[i] = run;
    run += deg[i];
  }
  if (hi == N && lo < N) rowptr[N] = run;
  if (N <= lo && tid == 0) rowptr[N] = 0; // degenerate safety
}

__global__ void k_scatter(const int* __restrict__ src, const int* __restrict__ dst, int E,
                          int* __restrict__ cursor, int* __restrict__ esrc){
  int t = blockIdx.x*blockDim.x + threadIdx.x;
  if (t >= E) return;
  int p = atomicAdd(&cursor[dst[t]], 1);
  esrc[p] = src[t];
}

// ---------------- GEMM: O[N,K] = A[N,F] @ W[F,K], K even ----------------
__global__ void k_gemm(const float* __restrict__ A, const float* __restrict__ W,
                       float* __restrict__ O, int N, int F, int K){
  int K2 = K >> 1;
  long long tid = (long long)blockIdx.x*blockDim.x + threadIdx.x;
  long long total = (long long)CDIV(N,4)*K2;
  if (tid >= total) return;
  int kk = (int)(tid % K2);
  int n0 = (int)(tid / K2) * 4;
  const float2* W2 = (const float2*)W;
  if (n0 + 4 <= N){
    const float* r0 = A + (size_t)n0*F;
    const float* r1 = r0 + F;
    const float* r2 = r1 + F;
    const float* r3 = r2 + F;
    float a0=0,c0=0,a1=0,c1=0,a2=0,c2=0,a3=0,c3=0;
    for (int f=0; f<F; ++f){
      float2 w = W2[(size_t)f*K2 + kk];
      float x0=r0[f], x1=r1[f], x2=r2[f], x3=r3[f];
      a0 = fmaf(x0,w.x,a0); c0 = fmaf(x0,w.y,c0);
      a1 = fmaf(x1,w.x,a1); c1 = fmaf(x1,w.y,c1);
      a2 = fmaf(x2,w.x,a2); c2 = fmaf(x2,w.y,c2);
      a3 = fmaf(x3,w.x,a3); c3 = fmaf(x3,w.y,c3);
    }
    O[(size_t)(n0+0)*K + 2*kk] = a0; O[(size_t)(n0+0)*K + 2*kk+1] = c0;
    O[(size_t)(n0+1)*K + 2*kk] = a1; O[(size_t)(n0+1)*K + 2*kk+1] = c1;
    O[(size_t)(n0+2)*K + 2*kk] = a2; O[(size_t)(n0+2)*K + 2*kk+1] = c2;
    O[(size_t)(n0+3)*K + 2*kk] = a3; O[(size_t)(n0+3)*K + 2*kk+1] = c3;
  } else {
    for (int r=0; r<4; ++r){
      int n = n0 + r;
      if (n >= N) break;
      float s0=0, s1=0;
      for (int f=0; f<F; ++f){
        float2 w = W2[(size_t)f*K2 + kk];
        float x = A[(size_t)n*F + f];
        s0 = fmaf(x,w.x,s0); s1 = fmaf(x,w.y,s1);
      }
      O[(size_t)n*K + 2*kk] = s0; O[(size_t)n*K + 2*kk+1] = s1;
    }
  }
}

// -------- per-(node,head) attention logits --------
__global__ void k_node_prep(const float* __restrict__ xw, const float* __restrict__ asrc,
                            const float* __restrict__ adst, int N, int H, int C,
                            float* __restrict__ as, float* __restrict__ ad){
  int t = blockIdx.x*blockDim.x + threadIdx.x;
  if (t >= N*H) return;
  int n = t / H, h = t - n*H;
  const float* row = xw + (size_t)n*H*C + (size_t)h*C;
  float s=0.f, d=0.f;
  for (int c=0; c<C; ++c){ float v = row[c]; s = fmaf(v, asrc[h*C+c], s); d = fmaf(v, adst[h*C+c], d); }
  as[t]=s; ad[t]=d;
}

// warp-per-node version for H==1, large C
__global__ void k_node_prep_w(const float* __restrict__ xw, const float* __restrict__ asrc,
                              const float* __restrict__ adst, int N, int C,
                              float* __restrict__ as, float* __restrict__ ad){
  int w = (blockIdx.x*blockDim.x + threadIdx.x) >> 5;
  int lane = threadIdx.x & 31;
  if (w >= N) return;
  const float* row = xw + (size_t)w*C;
  float s=0.f, d=0.f;
  for (int c=lane; c<C; c+=32){ float v = row[c]; s = fmaf(v, asrc[c], s); d = fmaf(v, adst[c], d); }
  for (int o=16; o; o>>=1){ s += __shfl_xor_sync(0xffffffffu, s, o); d += __shfl_xor_sync(0xffffffffu, d, o); }
  if (lane == 0){ as[w]=s; ad[w]=d; }
}

// -------- fused aggregation, H=8 C=8 (F=64): warp per dst node --------
// lane owns channels (2*lane, 2*lane+1); head h = lane>>2
__global__ void k_aggr8(const int* __restrict__ rowptr, const int* __restrict__ esrc,
                        const float* __restrict__ as, const float* __restrict__ ad,
                        const float* __restrict__ xw, const float* __restrict__ bias,
                        float* __restrict__ out, int N){
  int w = (int)(((long long)blockIdx.x*blockDim.x + threadIdx.x) >> 5);
  int lane = threadIdx.x & 31;
  if (w >= N) return;
  int h = lane >> 2;
  float adv = __ldg(&ad[w*8+h]);
  const float2* xw2 = (const float2*)xw;

  // self-loop
  float p = __expf(lrelu(__ldg(&as[w*8+h]) + adv));
  float2 xv = xw2[(size_t)w*32 + lane];
  float accx = p*xv.x, accy = p*xv.y, den = p;

  int k  = rowptr[w];
  int ke = rowptr[w+1];
  for (; k+1 < ke; k += 2){
    int s0 = __ldg(&esrc[k]);
    int s1 = __ldg(&esrc[k+1]);
    float p0 = __expf(lrelu(__ldg(&as[s0*8+h]) + adv));
    float p1 = __expf(lrelu(__ldg(&as[s1*8+h]) + adv));
    float2 v0 = xw2[(size_t)s0*32 + lane];
    float2 v1 = xw2[(size_t)s1*32 + lane];
    accx = fmaf(p0, v0.x, accx); accy = fmaf(p0, v0.y, accy);
    accx = fmaf(p1, v1.x, accx); accy = fmaf(p1, v1.y, accy);
    den += p0 + p1;
  }
  if (k < ke){
    int s0 = __ldg(&esrc[k]);
    float p0 = __expf(lrelu(__ldg(&as[s0*8+h]) + adv));
    float2 v0 = xw2[(size_t)s0*32 + lane];
    accx = fmaf(p0, v0.x, accx); accy = fmaf(p0, v0.y, accy);
    den += p0;
  }
  float inv = 1.f / (den + 1e-16f);
  float2 bv = ((const float2*)bias)[lane];
  float2 o;
  o.x = fmaxf(fmaf(accx, inv, bv.x), 0.f);
  o.y = fmaxf(fmaf(accy, inv, bv.y), 0.f);
  ((float2*)out)[(size_t)w*32 + lane] = o;
}

// -------- fused aggregation + final softmax, H=1 C=242: warp per dst node --------
// float2 slots j = lane + 32*t, t in [0,4), j < 121; slot j = channel pair (2j, 2j+1)
__global__ void k_aggr1(const int* __restrict__ rowptr, const int* __restrict__ esrc,
                        const float* __restrict__ as, const float* __restrict__ ad,
                        const float* __restrict__ xw, const float* __restrict__ bias,
                        float* __restrict__ out, int N){
  int w = (int)(((long long)blockIdx.x*blockDim.x + threadIdx.x) >> 5);
  int lane = threadIdx.x & 31;
  if (w >= N) return;
  float adv = __ldg(&ad[w]);

  float accx[4] = {0,0,0,0}, accy[4] = {0,0,0,0};
  float den;
  // self-loop
  {
    float p = __expf(lrelu(__ldg(&as[w]) + adv));
    den = p;
    const float2* xs = (const float2*)(xw + (size_t)w*242);
    #pragma unroll
    for (int t = 0; t < 4; ++t){
      int j = lane + 32*t;
      if (j < 121){ float2 v = xs[j]; accx[t] = p*v.x; accy[t] = p*v.y; }
    }
  }
  int k  = rowptr[w];
  int ke = rowptr[w+1];
  for (; k+1 < ke; k += 2){
    int s0 = __ldg(&esrc[k]);
    int s1 = __ldg(&esrc[k+1]);
    float p0 = __expf(lrelu(__ldg(&as[s0]) + adv));
    float p1 = __expf(lrelu(__ldg(&as[s1]) + adv));
    const float2* x0 = (const float2*)(xw + (size_t)s0*242);
    const float2* x1 = (const float2*)(xw + (size_t)s1*242);
    den += p0 + p1;
    #pragma unroll
    for (int t = 0; t < 4; ++t){
      int j = lane + 32*t;
      if (j < 121){
        float2 v0 = x0[j], v1 = x1[j];
        accx[t] = fmaf(p0, v0.x, accx[t]); accy[t] = fmaf(p0, v0.y, accy[t]);
        accx[t] = fmaf(p1, v1.x, accx[t]); accy[t] = fmaf(p1, v1.y, accy[t]);
      }
    }
  }
  if (k < ke){
    int s0 = __ldg(&esrc[k]);
    float p0 = __expf(lrelu(__ldg(&as[s0]) + adv));
    const float2* x0 = (const float2*)(xw + (size_t)s0*242);
    den += p0;
    #pragma unroll
    for (int t = 0; t < 4; ++t){
      int j = lane + 32*t;
      if (j < 121){
        float2 v0 = x0[j];
        accx[t] = fmaf(p0, v0.x, accx[t]); accy[t] = fmaf(p0, v0.y, accy[t]);
      }
    }
  }
  float inv = 1.f / (den + 1e-16f);
  float2* od = (float2*)(out + (size_t)w*242);
  const float2* b2 = (const float2*)bias;
  #pragma unroll
  for (int t = 0; t < 4; ++t){
    int j = lane + 32*t;
    if (j < 121){
      float2 bv = b2[j];
      float v0 = fmaxf(fmaf(accx[t], inv, bv.x), 0.f);
      float v1 = fmaxf(fmaf(accy[t], inv, bv.y), 0.f);
      float m = fmaxf(v0, v1);
      float e0 = __expf(v0 - m), e1 = __expf(v1 - m);
      float r = 1.f / (e0 + e1);
      float2 o; o.x = e0*r; o.y = e1*r;
      od[j] = o;
    }
  }
}

// ---------------- host side ----------------
struct Scratch {
  float *xw, *h0, *h1, *as, *ad;
  int *deg, *rowptr, *cursor, *esrc;
};

static void gat_layer(const float* hin, int Fin, int K, int H, int C,
                      const float* W, const float* asrc, const float* adst, const float* bias,
                      int N, const Scratch& S, float* out){
  const int B = 256;
  long long gth = (long long)CDIV(N,4)*(K/2);
  k_gemm<<<(unsigned)CDIV(gth,B), B>>>(hin, W, S.xw, N, Fin, K);
  if (H > 1){
    k_node_prep<<<CDIV(N*H,B), B>>>(S.xw, asrc, adst, N, H, C, S.as, S.ad);
    k_aggr8<<<(unsigned)CDIV((long long)N*32,B), B>>>(S.rowptr, S.esrc, S.as, S.ad, S.xw, bias, out, N);
  } else {
    k_node_prep_w<<<CDIV(N*32,B), B>>>(S.xw, asrc, adst, N, C, S.as, S.ad);
    k_aggr1<<<(unsigned)CDIV((long long)N*32,B), B>>>(S.rowptr, S.esrc, S.as, S.ad, S.xw, bias, out, N);
  }
}

extern "C" void kernel_launch(void* const* d_in, const int* in_sizes, int n_in,
                              void* d_out, int out_size){
  const float* x  = (const float*)d_in[0];
  const int*   ei = (const int*)d_in[1];          // int32
  const float *W1=(const float*)d_in[2],  *a1s=(const float*)d_in[3],  *a1d=(const float*)d_in[4],  *b1=(const float*)d_in[5];
  const float *W2=(const float*)d_in[6],  *a2s=(const float*)d_in[7],  *a2d=(const float*)d_in[8],  *b2=(const float*)d_in[9];
  const float *W3=(const float*)d_in[10], *a3s=(const float*)d_in[11], *a3d=(const float*)d_in[12], *b3=(const float*)d_in[13];
  int N = in_sizes[0] / 128;
  int E = in_sizes[1] / 2;
  const int* src = ei;
  const int* dst = ei + E;

  Scratch S;
  cudaGetSymbolAddress((void**)&S.xw,     g_xw);
  cudaGetSymbolAddress((void**)&S.h0,     g_h0);
  cudaGetSymbolAddress((void**)&S.h1,     g_h1);
  cudaGetSymbolAddress((void**)&S.as,     g_as);
  cudaGetSymbolAddress((void**)&S.ad,     g_ad);
  cudaGetSymbolAddress((void**)&S.deg,    g_deg);
  cudaGetSymbolAddress((void**)&S.rowptr, g_rowptr);
  cudaGetSymbolAddress((void**)&S.cursor, g_cursor);
  cudaGetSymbolAddress((void**)&S.esrc,   g_esrc);

  const int B = 256;
  // CSR build (dst-sorted), once per call
  cudaMemsetAsync(S.deg, 0, (size_t)N*sizeof(int));
  k_hist<<<CDIV(E,B), B>>>(dst, E, S.deg);
  k_scan<<<1, 1024>>>(S.deg, S.rowptr, S.cursor, N);
  k_scatter<<<CDIV(E,B), B>>>(src, dst, E, S.cursor, S.esrc);

  // Layer 1: 128 -> 64, H=8, C=8, concat
  gat_layer(x,    128, 64,  8, 8,   W1, a1s, a1d, b1, N, S, S.h0);
  // Layer 2: 64 -> 64, H=8, C=8, concat
  gat_layer(S.h0, 64,  64,  8, 8,   W2, a2s, a2d, b2, N, S, S.h1);
  // Layer 3: 64 -> 242, H=1, C=242, mean (=identity), relu, pairwise softmax
  gat_layer(S.h1, 64,  242, 1, 242, W3, a3s, a3d, b3, N, S, (float*)d_out);
}

// round 8
// speedup vs baseline: 1.7497x; 1.0596x over previous
#include <cuda_runtime.h>

#define CDIV(a,b) (((a)+(b)-1)/(b))
typedef unsigned long long ull;

static const int NMAX = 50000;
static const int EMAX = 800000;

// Scratch (device globals — no allocation allowed)
__device__ __align__(16) float g_xw  [(size_t)NMAX*242];
__device__ __align__(16) float g_h0  [(size_t)NMAX*64];
__device__ __align__(16) float g_h1  [(size_t)NMAX*64];
__device__ __align__(16) float g_as  [NMAX*8];
__device__ __align__(16) float g_ad  [NMAX*8];
__device__ int g_deg   [NMAX];
__device__ int g_rowptr[NMAX+1];
__device__ int g_cursor[NMAX];
__device__ int g_esrc  [EMAX];

__device__ __forceinline__ float lrelu(float x){ return x > 0.f ? x : 0.2f*x; }

// ---- f32x2 packed helpers (FFMA2 path, sm_100+) ----
__device__ __forceinline__ ull pack2(float x, float y){
  ull d; asm("mov.b64 %0, {%1,%2};" : "=l"(d) : "f"(x), "f"(y)); return d;
}
__device__ __forceinline__ ull ffma2(ull a, ull b, ull c){
  ull r; asm("fma.rn.f32x2 %0, %1, %2, %3;" : "=l"(r) : "l"(a), "l"(b), "l"(c)); return r;
}
__device__ __forceinline__ float2 unpack2(ull d){
  float2 v; asm("mov.b64 {%0,%1}, %2;" : "=f"(v.x), "=f"(v.y) : "l"(d)); return v;
}

// ---------------- CSR build ----------------
__global__ void k_hist(const int* __restrict__ dst, int E, int* __restrict__ deg){
  int t = blockIdx.x*blockDim.x + threadIdx.x;
  if (t < E) atomicAdd(&deg[dst[t]], 1);
}

__global__ void k_scan(const int* __restrict__ deg, int* __restrict__ rowptr,
                       int* __restrict__ cursor, int N){
  __shared__ int partial[1024];
  int tid = threadIdx.x;
  int chunk = CDIV(N, 1024);
  int lo = tid*chunk, hi = min(lo+chunk, N);
  int s = 0;
  for (int i = lo; i < hi; ++i) s += deg[i];
  partial[tid] = s;
  __syncthreads();
  for (int off = 1; off < 1024; off <<= 1){
    int v = (tid >= off) ? partial[tid-off] : 0;
    __syncthreads();
    partial[tid] += v;
    __syncthreads();
  }
  int run = partial[tid] - s;   // exclusive base for this chunk
  for (int i = lo; i < hi; ++i){
    rowptr[i] = run; cursor[i] = run;
    run += deg[i];
  }
  if (hi == N && lo < N) rowptr[N] = run;
  if (N <= lo && tid == 0) rowptr[N] = 0;
}

__global__ void k_scatter(const int* __restrict__ src, const int* __restrict__ dst, int E,
                          int* __restrict__ cursor, int* __restrict__ esrc){
  int t = blockIdx.x*blockDim.x + threadIdx.x;
  if (t >= E) return;
  int p = atomicAdd(&cursor[dst[t]], 1);
  esrc[p] = src[t];
}

// ---------------- GEMM K=64 (layers 1/2): f32x2, 4 rows x 4 cols / thread ----
// blockDim 256: kt = tid&15 (4 cols), rg = tid>>4 (16 row groups of 4) -> 64 rows/block
__global__ void k_gemm64(const float* __restrict__ A, const float* __restrict__ W,
                         float* __restrict__ O, int N, int F){
  const int K = 64;
  int kt = threadIdx.x & 15;
  int rg = threadIdx.x >> 4;
  int row0 = (blockIdx.x*16 + rg)*4;
  if (row0 >= N) return;
  int c0 = kt*4;
  ull acc[4][2];
  #pragma unroll
  for (int r=0;r<4;++r){ acc[r][0]=0ull; acc[r][1]=0ull; }
  int rr[4];
  #pragma unroll
  for (int r=0;r<4;++r) rr[r] = min(row0+r, N-1);

  for (int f=0; f<F; f+=4){
    ulonglong2 w[4];
    #pragma unroll
    for (int u=0; u<4; ++u)
      w[u] = *(const ulonglong2*)(W + (size_t)(f+u)*K + c0);
    #pragma unroll
    for (int r=0; r<4; ++r){
      float4 a = *(const float4*)(A + (size_t)rr[r]*F + f);
      ull ax = pack2(a.x,a.x), ay = pack2(a.y,a.y), az = pack2(a.z,a.z), aw = pack2(a.w,a.w);
      acc[r][0] = ffma2(ax, w[0].x, acc[r][0]); acc[r][1] = ffma2(ax, w[0].y, acc[r][1]);
      acc[r][0] = ffma2(ay, w[1].x, acc[r][0]); acc[r][1] = ffma2(ay, w[1].y, acc[r][1]);
      acc[r][0] = ffma2(az, w[2].x, acc[r][0]); acc[r][1] = ffma2(az, w[2].y, acc[r][1]);
      acc[r][0] = ffma2(aw, w[3].x, acc[r][0]); acc[r][1] = ffma2(aw, w[3].y, acc[r][1]);
    }
  }
  #pragma unroll
  for (int r=0; r<4; ++r){
    if (row0+r < N){
      float2 lo = unpack2(acc[r][0]), hi = unpack2(acc[r][1]);
      float4 o; o.x=lo.x; o.y=lo.y; o.z=hi.x; o.w=hi.y;
      *(float4*)(O + (size_t)(row0+r)*K + c0) = o;
    }
  }
}

// ---------------- GEMM K=242 (layer 3): f32x2, 4 rows x 2 cols / thread ----
// blockDim 242: kt = tid%121, rg = tid/121 (2 row groups of 4) -> 8 rows/block
__global__ void k_gemm242(const float* __restrict__ A, const float* __restrict__ W,
                          float* __restrict__ O, int N){
  const int K = 242, F = 64;
  int kt = threadIdx.x % 121;
  int rg = threadIdx.x / 121;
  int row0 = (blockIdx.x*2 + rg)*4;
  if (row0 >= N) return;
  int c0 = kt*2;
  ull acc[4] = {0ull,0ull,0ull,0ull};
  int rr[4];
  #pragma unroll
  for (int r=0;r<4;++r) rr[r] = min(row0+r, N-1);

  for (int f=0; f<F; f+=4){
    ull w0 = *(const ull*)(W + (size_t)(f+0)*K + c0);
    ull w1 = *(const ull*)(W + (size_t)(f+1)*K + c0);
    ull w2 = *(const ull*)(W + (size_t)(f+2)*K + c0);
    ull w3 = *(const ull*)(W + (size_t)(f+3)*K + c0);
    #pragma unroll
    for (int r=0; r<4; ++r){
      float4 a = *(const float4*)(A + (size_t)rr[r]*F + f);
      acc[r] = ffma2(pack2(a.x,a.x), w0, acc[r]);
      acc[r] = ffma2(pack2(a.y,a.y), w1, acc[r]);
      acc[r] = ffma2(pack2(a.z,a.z), w2, acc[r]);
      acc[r] = ffma2(pack2(a.w,a.w), w3, acc[r]);
    }
  }
  #pragma unroll
  for (int r=0; r<4; ++r){
    if (row0+r < N){
      float2 v = unpack2(acc[r]);
      *(float2*)(O + (size_t)(row0+r)*K + c0) = v;   // 8B aligned: 968*row + 8*kt
    }
  }
}

// -------- per-(node,head) attention logits --------
__global__ void k_node_prep(const float* __restrict__ xw, const float* __restrict__ asrc,
                            const float* __restrict__ adst, int N, int H, int C,
                            float* __restrict__ as, float* __restrict__ ad){
  int t = blockIdx.x*blockDim.x + threadIdx.x;
  if (t >= N*H) return;
  int n = t / H, h = t - n*H;
  const float* row = xw + (size_t)n*H*C + (size_t)h*C;
  float s=0.f, d=0.f;
  for (int c=0; c<C; ++c){ float v = row[c]; s = fmaf(v, asrc[h*C+c], s); d = fmaf(v, adst[h*C+c], d); }
  as[t]=s; ad[t]=d;
}

// warp-per-node version for H==1, large C
__global__ void k_node_prep_w(const float* __restrict__ xw, const float* __restrict__ asrc,
                              const float* __restrict__ adst, int N, int C,
                              float* __restrict__ as, float* __restrict__ ad){
  int w = (blockIdx.x*blockDim.x + threadIdx.x) >> 5;
  int lane = threadIdx.x & 31;
  if (w >= N) return;
  const float* row = xw + (size_t)w*C;
  float s=0.f, d=0.f;
  for (int c=lane; c<C; c+=32){ float v = row[c]; s = fmaf(v, asrc[c], s); d = fmaf(v, adst[c], d); }
  for (int o=16; o; o>>=1){ s += __shfl_xor_sync(0xffffffffu, s, o); d += __shfl_xor_sync(0xffffffffu, d, o); }
  if (lane == 0){ as[w]=s; ad[w]=d; }
}

// -------- fused aggregation, H=8 C=8 (F=64): warp per dst node --------
__global__ void k_aggr8(const int* __restrict__ rowptr, const int* __restrict__ esrc,
                        const float* __restrict__ as, const float* __restrict__ ad,
                        const float* __restrict__ xw, const float* __restrict__ bias,
                        float* __restrict__ out, int N){
  int w = (int)(((long long)blockIdx.x*blockDim.x + threadIdx.x) >> 5);
  int lane = threadIdx.x & 31;
  if (w >= N) return;
  int h = lane >> 2;
  float adv = __ldg(&ad[w*8+h]);
  const float2* xw2 = (const float2*)xw;

  // self-loop
  float p = __expf(lrelu(__ldg(&as[w*8+h]) + adv));
  float2 xv = xw2[(size_t)w*32 + lane];
  float accx = p*xv.x, accy = p*xv.y, den = p;

  int k  = rowptr[w];
  int ke = rowptr[w+1];
  for (; k+1 < ke; k += 2){
    int s0 = __ldg(&esrc[k]);
    int s1 = __ldg(&esrc[k+1]);
    float p0 = __expf(lrelu(__ldg(&as[s0*8+h]) + adv));
    float p1 = __expf(lrelu(__ldg(&as[s1*8+h]) + adv));
    float2 v0 = xw2[(size_t)s0*32 + lane];
    float2 v1 = xw2[(size_t)s1*32 + lane];
    accx = fmaf(p0, v0.x, accx); accy = fmaf(p0, v0.y, accy);
    accx = fmaf(p1, v1.x, accx); accy = fmaf(p1, v1.y, accy);
    den += p0 + p1;
  }
  if (k < ke){
    int s0 = __ldg(&esrc[k]);
    float p0 = __expf(lrelu(__ldg(&as[s0*8+h]) + adv));
    float2 v0 = xw2[(size_t)s0*32 + lane];
    accx = fmaf(p0, v0.x, accx); accy = fmaf(p0, v0.y, accy);
    den += p0;
  }
  float inv = 1.f / (den + 1e-16f);
  float2 bv = ((const float2*)bias)[lane];
  float2 o;
  o.x = fmaxf(fmaf(accx, inv, bv.x), 0.f);
  o.y = fmaxf(fmaf(accy, inv, bv.y), 0.f);
  ((float2*)out)[(size_t)w*32 + lane] = o;
}

// -------- fused aggregation + final softmax, H=1 C=242: warp per dst node --------
__global__ void k_aggr1(const int* __restrict__ rowptr, const int* __restrict__ esrc,
                        const float* __restrict__ as, const float* __restrict__ ad,
                        const float* __restrict__ xw, const float* __restrict__ bias,
                        float* __restrict__ out, int N){
  int w = (int)(((long long)blockIdx.x*blockDim.x + threadIdx.x) >> 5);
  int lane = threadIdx.x & 31;
  if (w >= N) return;
  float adv = __ldg(&ad[w]);

  float accx[4] = {0,0,0,0}, accy[4] = {0,0,0,0};
  float den;
  // self-loop
  {
    float p = __expf(lrelu(__ldg(&as[w]) + adv));
    den = p;
    const float2* xs = (const float2*)(xw + (size_t)w*242);
    #pragma unroll
    for (int t = 0; t < 4; ++t){
      int j = lane + 32*t;
      if (j < 121){ float2 v = xs[j]; accx[t] = p*v.x; accy[t] = p*v.y; }
    }
  }
  int k  = rowptr[w];
  int ke = rowptr[w+1];
  for (; k+1 < ke; k += 2){
    int s0 = __ldg(&esrc[k]);
    int s1 = __ldg(&esrc[k+1]);
    float p0 = __expf(lrelu(__ldg(&as[s0]) + adv));
    float p1 = __expf(lrelu(__ldg(&as[s1]) + adv));
    const float2* x0 = (const float2*)(xw + (size_t)s0*242);
    const float2* x1 = (const float2*)(xw + (size_t)s1*242);
    den += p0 + p1;
    #pragma unroll
    for (int t = 0; t < 4; ++t){
      int j = lane + 32*t;
      if (j < 121){
        float2 v0 = x0[j], v1 = x1[j];
        accx[t] = fmaf(p0, v0.x, accx[t]); accy[t] = fmaf(p0, v0.y, accy[t]);
        accx[t] = fmaf(p1, v1.x, accx[t]); accy[t] = fmaf(p1, v1.y, accy[t]);
      }
    }
  }
  if (k < ke){
    int s0 = __ldg(&esrc[k]);
    float p0 = __expf(lrelu(__ldg(&as[s0]) + adv));
    const float2* x0 = (const float2*)(xw + (size_t)s0*242);
    den += p0;
    #pragma unroll
    for (int t = 0; t < 4; ++t){
      int j = lane + 32*t;
      if (j < 121){
        float2 v0 = x0[j];
        accx[t] = fmaf(p0, v0.x, accx[t]); accy[t] = fmaf(p0, v0.y, accy[t]);
      }
    }
  }
  float inv = 1.f / (den + 1e-16f);
  float2* od = (float2*)(out + (size_t)w*242);
  const float2* b2 = (const float2*)bias;
  #pragma unroll
  for (int t = 0; t < 4; ++t){
    int j = lane + 32*t;
    if (j < 121){
      float2 bv = b2[j];
      float v0 = fmaxf(fmaf(accx[t], inv, bv.x), 0.f);
      float v1 = fmaxf(fmaf(accy[t], inv, bv.y), 0.f);
      float m = fmaxf(v0, v1);
      float e0 = __expf(v0 - m), e1 = __expf(v1 - m);
      float r = 1.f / (e0 + e1);
      float2 o; o.x = e0*r; o.y = e1*r;
      od[j] = o;
    }
  }
}

// ---------------- host side ----------------
struct Scratch {
  float *xw, *h0, *h1, *as, *ad;
  int *deg, *rowptr, *cursor, *esrc;
};

extern "C" void kernel_launch(void* const* d_in, const int* in_sizes, int n_in,
                              void* d_out, int out_size){
  const float* x  = (const float*)d_in[0];
  const int*   ei = (const int*)d_in[1];          // int32
  const float *W1=(const float*)d_in[2],  *a1s=(const float*)d_in[3],  *a1d=(const float*)d_in[4],  *b1=(const float*)d_in[5];
  const float *W2=(const float*)d_in[6],  *a2s=(const float*)d_in[7],  *a2d=(const float*)d_in[8],  *b2=(const float*)d_in[9];
  const float *W3=(const float*)d_in[10], *a3s=(const float*)d_in[11], *a3d=(const float*)d_in[12], *b3=(const float*)d_in[13];
  int N = in_sizes[0] / 128;
  int E = in_sizes[1] / 2;
  const int* src = ei;
  const int* dst = ei + E;

  Scratch S;
  cudaGetSymbolAddress((void**)&S.xw,     g_xw);
  cudaGetSymbolAddress((void**)&S.h0,     g_h0);
  cudaGetSymbolAddress((void**)&S.h1,     g_h1);
  cudaGetSymbolAddress((void**)&S.as,     g_as);
  cudaGetSymbolAddress((void**)&S.ad,     g_ad);
  cudaGetSymbolAddress((void**)&S.deg,    g_deg);
  cudaGetSymbolAddress((void**)&S.rowptr, g_rowptr);
  cudaGetSymbolAddress((void**)&S.cursor, g_cursor);
  cudaGetSymbolAddress((void**)&S.esrc,   g_esrc);

  const int B = 256;
  // CSR build (dst-sorted), once per call
  cudaMemsetAsync(S.deg, 0, (size_t)N*sizeof(int));
  k_hist<<<CDIV(E,B), B>>>(dst, E, S.deg);
  k_scan<<<1, 1024>>>(S.deg, S.rowptr, S.cursor, N);
  k_scatter<<<CDIV(E,B), B>>>(src, dst, E, S.cursor, S.esrc);

  // Layer 1: 128 -> 64, H=8, C=8
  k_gemm64<<<CDIV(N,64), 256>>>(x, W1, S.xw, N, 128);
  k_node_prep<<<CDIV(N*8,B), B>>>(S.xw, a1s, a1d, N, 8, 8, S.as, S.ad);
  k_aggr8<<<(unsigned)CDIV((long long)N*32,B), B>>>(S.rowptr, S.esrc, S.as, S.ad, S.xw, b1, S.h0, N);

  // Layer 2: 64 -> 64, H=8, C=8
  k_gemm64<<<CDIV(N,64), 256>>>(S.h0, W2, S.xw, N, 64);
  k_node_prep<<<CDIV(N*8,B), B>>>(S.xw, a2s, a2d, N, 8, 8, S.as, S.ad);
  k_aggr8<<<(unsigned)CDIV((long long)N*32,B), B>>>(S.rowptr, S.esrc, S.as, S.ad, S.xw, b2, S.h1, N);

  // Layer 3: 64 -> 242, H=1, C=242, relu + pairwise softmax fused
  k_gemm242<<<CDIV(N,8), 242>>>(S.h1, W3, S.xw, N);
  k_node_prep_w<<<CDIV(N*32,B), B>>>(S.xw, a3s, a3d, N, 242, S.as, S.ad);
  k_aggr1<<<(unsigned)CDIV((long long)N*32,B), B>>>(S.rowptr, S.esrc, S.as, S.ad, S.xw, b3, (float*)d_out, N);
}

// round 9
// speedup vs baseline: 1.9391x; 1.1083x over previous
#include <cuda_runtime.h>

#define CDIV(a,b) (((a)+(b)-1)/(b))
typedef unsigned long long ull;

static const int NMAX = 50000;
static const int EMAX = 800000;

// Scratch (device globals — no allocation allowed)
__device__ __align__(16) float g_xw  [(size_t)NMAX*242];
__device__ __align__(16) float g_h0  [(size_t)NMAX*64];
__device__ __align__(16) float g_h1  [(size_t)NMAX*64];
__device__ __align__(16) float g_as  [NMAX*8];
__device__ __align__(16) float g_ad  [NMAX*8];
__device__ __align__(16) float g_v   [128];        // vsrc[64], vdst[64] for layer 3
__device__ int g_deg   [NMAX];
__device__ int g_rowptr[NMAX+1];
__device__ int g_cursor[NMAX];
__device__ int g_esrc  [EMAX];

__device__ __forceinline__ float lrelu(float x){ return x > 0.f ? x : 0.2f*x; }

// ---- f32x2 packed helpers (FFMA2 path, sm_100+) ----
__device__ __forceinline__ ull pack2(float x, float y){
  ull d; asm("mov.b64 %0, {%1,%2};" : "=l"(d) : "f"(x), "f"(y)); return d;
}
__device__ __forceinline__ ull ffma2(ull a, ull b, ull c){
  ull r; asm("fma.rn.f32x2 %0, %1, %2, %3;" : "=l"(r) : "l"(a), "l"(b), "l"(c)); return r;
}
__device__ __forceinline__ float2 unpack2(ull d){
  float2 v; asm("mov.b64 {%0,%1}, %2;" : "=f"(v.x), "=f"(v.y) : "l"(d)); return v;
}

// ---------------- CSR build ----------------
__global__ void k_hist(const int* __restrict__ dst, int E, int* __restrict__ deg){
  int t = blockIdx.x*blockDim.x + threadIdx.x;
  if (t < E) atomicAdd(&deg[dst[t]], 1);
}

__global__ void k_scan(const int* __restrict__ deg, int* __restrict__ rowptr,
                       int* __restrict__ cursor, int N){
  __shared__ int partial[1024];
  int tid = threadIdx.x;
  int chunk = CDIV(N, 1024);
  int lo = tid*chunk, hi = min(lo+chunk, N);
  int s = 0;
  for (int i = lo; i < hi; ++i) s += deg[i];
  partial[tid] = s;
  __syncthreads();
  for (int off = 1; off < 1024; off <<= 1){
    int v = (tid >= off) ? partial[tid-off] : 0;
    __syncthreads();
    partial[tid] += v;
    __syncthreads();
  }
  int run = partial[tid] - s;   // exclusive base for this chunk
  for (int i = lo; i < hi; ++i){
    rowptr[i] = run; cursor[i] = run;
    run += deg[i];
  }
  if (hi == N && lo < N) rowptr[N] = run;
  if (N <= lo && tid == 0) rowptr[N] = 0;
}

__global__ void k_scatter(const int* __restrict__ src, const int* __restrict__ dst, int E,
                          int* __restrict__ cursor, int* __restrict__ esrc){
  int t = blockIdx.x*blockDim.x + threadIdx.x;
  if (t >= E) return;
  int p = atomicAdd(&cursor[dst[t]], 1);
  esrc[p] = src[t];
}

// ---------------- GEMM K=64 (layers 1/2): SMEM-staged W, f32x2 ----------------
// blockDim 256: kt = tid&15 (4 cols), rg = tid>>4 -> 64 rows/block
__global__ __launch_bounds__(256) void k_gemm64(
    const float* __restrict__ A, const float* __restrict__ W,
    float* __restrict__ O, int N, int F){
  const int K = 64;
  __shared__ float sW[128*64];          // up to F=128
  for (int i = threadIdx.x; i < (F*K)/4; i += 256)
    ((float4*)sW)[i] = ((const float4*)W)[i];
  __syncthreads();

  int kt = threadIdx.x & 15;
  int rg = threadIdx.x >> 4;
  int row0 = (blockIdx.x*16 + rg)*4;
  if (row0 >= N) return;
  int c0 = kt*4;
  ull acc[4][2];
  #pragma unroll
  for (int r=0;r<4;++r){ acc[r][0]=0ull; acc[r][1]=0ull; }
  int rr[4];
  #pragma unroll
  for (int r=0;r<4;++r) rr[r] = min(row0+r, N-1);

  for (int f=0; f<F; f+=4){
    ulonglong2 w[4];
    #pragma unroll
    for (int u=0; u<4; ++u)
      w[u] = *(const ulonglong2*)(sW + (f+u)*K + c0);
    #pragma unroll
    for (int r=0; r<4; ++r){
      float4 a = *(const float4*)(A + (size_t)rr[r]*F + f);
      ull ax = pack2(a.x,a.x), ay = pack2(a.y,a.y), az = pack2(a.z,a.z), aw = pack2(a.w,a.w);
      acc[r][0] = ffma2(ax, w[0].x, acc[r][0]); acc[r][1] = ffma2(ax, w[0].y, acc[r][1]);
      acc[r][0] = ffma2(ay, w[1].x, acc[r][0]); acc[r][1] = ffma2(ay, w[1].y, acc[r][1]);
      acc[r][0] = ffma2(az, w[2].x, acc[r][0]); acc[r][1] = ffma2(az, w[2].y, acc[r][1]);
      acc[r][0] = ffma2(aw, w[3].x, acc[r][0]); acc[r][1] = ffma2(aw, w[3].y, acc[r][1]);
    }
  }
  #pragma unroll
  for (int r=0; r<4; ++r){
    if (row0+r < N){
      float2 lo = unpack2(acc[r][0]), hi = unpack2(acc[r][1]);
      float4 o; o.x=lo.x; o.y=lo.y; o.z=hi.x; o.w=hi.y;
      *(float4*)(O + (size_t)(row0+r)*K + c0) = o;
    }
  }
}

// -------- per-(node,head) attention logits (layers 1/2) --------
__global__ void k_node_prep(const float* __restrict__ xw, const float* __restrict__ asrc,
                            const float* __restrict__ adst, int N, int H, int C,
                            float* __restrict__ as, float* __restrict__ ad){
  int t = blockIdx.x*blockDim.x + threadIdx.x;
  if (t >= N*H) return;
  int n = t / H, h = t - n*H;
  const float* row = xw + (size_t)n*H*C + (size_t)h*C;
  float s=0.f, d=0.f;
  for (int c=0; c<C; ++c){ float v = row[c]; s = fmaf(v, asrc[h*C+c], s); d = fmaf(v, adst[h*C+c], d); }
  as[t]=s; ad[t]=d;
}

// -------- fused aggregation, H=8 C=8 (F=64): warp per dst node --------
__global__ void k_aggr8(const int* __restrict__ rowptr, const int* __restrict__ esrc,
                        const float* __restrict__ as, const float* __restrict__ ad,
                        const float* __restrict__ xw, const float* __restrict__ bias,
                        float* __restrict__ out, int N){
  int w = (int)(((long long)blockIdx.x*blockDim.x + threadIdx.x) >> 5);
  int lane = threadIdx.x & 31;
  if (w >= N) return;
  int h = lane >> 2;
  float adv = __ldg(&ad[w*8+h]);
  const float2* xw2 = (const float2*)xw;

  // self-loop
  float p = __expf(lrelu(__ldg(&as[w*8+h]) + adv));
  float2 xv = xw2[(size_t)w*32 + lane];
  float accx = p*xv.x, accy = p*xv.y, den = p;

  int k  = rowptr[w];
  int ke = rowptr[w+1];
  for (; k+1 < ke; k += 2){
    int s0 = __ldg(&esrc[k]);
    int s1 = __ldg(&esrc[k+1]);
    float p0 = __expf(lrelu(__ldg(&as[s0*8+h]) + adv));
    float p1 = __expf(lrelu(__ldg(&as[s1*8+h]) + adv));
    float2 v0 = xw2[(size_t)s0*32 + lane];
    float2 v1 = xw2[(size_t)s1*32 + lane];
    accx = fmaf(p0, v0.x, accx); accy = fmaf(p0, v0.y, accy);
    accx = fmaf(p1, v1.x, accx); accy = fmaf(p1, v1.y, accy);
    den += p0 + p1;
  }
  if (k < ke){
    int s0 = __ldg(&esrc[k]);
    float p0 = __expf(lrelu(__ldg(&as[s0*8+h]) + adv));
    float2 v0 = xw2[(size_t)s0*32 + lane];
    accx = fmaf(p0, v0.x, accx); accy = fmaf(p0, v0.y, accy);
    den += p0;
  }
  float inv = 1.f / (den + 1e-16f);
  float2 bv = ((const float2*)bias)[lane];
  float2 o;
  o.x = fmaxf(fmaf(accx, inv, bv.x), 0.f);
  o.y = fmaxf(fmaf(accy, inv, bv.y), 0.f);
  ((float2*)out)[(size_t)w*32 + lane] = o;
}

// ======== Layer 3 (linearity: aggregate h1 first, project after) ========

// v[0:64] = W3 @ a3s, v[64:128] = W3 @ a3d   (one block, 64 threads)
__global__ void k_prepvec(const float* __restrict__ W3, const float* __restrict__ a3s,
                          const float* __restrict__ a3d, float* __restrict__ v){
  int f = threadIdx.x;           // 0..63
  const float* row = W3 + (size_t)f*242;
  float s=0.f, d=0.f;
  for (int c=0; c<242; ++c){ float w = row[c]; s = fmaf(w, a3s[c], s); d = fmaf(w, a3d[c], d); }
  v[f] = s; v[64+f] = d;
}

// as[n] = h[n]·v[0:64], ad[n] = h[n]·v[64:128]  (warp per node)
__global__ void k_dot64(const float* __restrict__ h, const float* __restrict__ v,
                        float* __restrict__ as, float* __restrict__ ad, int N){
  int w = (int)(((long long)blockIdx.x*blockDim.x + threadIdx.x) >> 5);
  int lane = threadIdx.x & 31;
  if (w >= N) return;
  float2 hv = ((const float2*)h)[(size_t)w*32 + lane];
  float2 vs = ((const float2*)v)[lane];
  float2 vd = ((const float2*)v)[32 + lane];
  float s = hv.x*vs.x + hv.y*vs.y;
  float d = hv.x*vd.x + hv.y*vd.y;
  #pragma unroll
  for (int o=16; o; o>>=1){ s += __shfl_xor_sync(0xffffffffu, s, o); d += __shfl_xor_sync(0xffffffffu, d, o); }
  if (lane == 0){ as[w]=s; ad[w]=d; }
}

// 64-dim aggregation with softmax weights, normalized output (warp per node)
__global__ void k_aggr64(const int* __restrict__ rowptr, const int* __restrict__ esrc,
                         const float* __restrict__ as, const float* __restrict__ ad,
                         const float* __restrict__ h, float* __restrict__ agg, int N){
  int w = (int)(((long long)blockIdx.x*blockDim.x + threadIdx.x) >> 5);
  int lane = threadIdx.x & 31;
  if (w >= N) return;
  float adv = __ldg(&ad[w]);
  const float2* h2 = (const float2*)h;

  // self-loop
  float p = __expf(lrelu(__ldg(&as[w]) + adv));
  float2 xv = h2[(size_t)w*32 + lane];
  float accx = p*xv.x, accy = p*xv.y, den = p;

  int k  = rowptr[w];
  int ke = rowptr[w+1];
  for (; k+1 < ke; k += 2){
    int s0 = __ldg(&esrc[k]);
    int s1 = __ldg(&esrc[k+1]);
    float p0 = __expf(lrelu(__ldg(&as[s0]) + adv));
    float p1 = __expf(lrelu(__ldg(&as[s1]) + adv));
    float2 v0 = h2[(size_t)s0*32 + lane];
    float2 v1 = h2[(size_t)s1*32 + lane];
    accx = fmaf(p0, v0.x, accx); accy = fmaf(p0, v0.y, accy);
    accx = fmaf(p1, v1.x, accx); accy = fmaf(p1, v1.y, accy);
    den += p0 + p1;
  }
  if (k < ke){
    int s0 = __ldg(&esrc[k]);
    float p0 = __expf(lrelu(__ldg(&as[s0]) + adv));
    float2 v0 = h2[(size_t)s0*32 + lane];
    accx = fmaf(p0, v0.x, accx); accy = fmaf(p0, v0.y, accy);
    den += p0;
  }
  float inv = 1.f / (den + 1e-16f);
  float2 o; o.x = accx*inv; o.y = accy*inv;
  ((float2*)agg)[(size_t)w*32 + lane] = o;
}

// final GEMM [N,64]@[64,242] + bias + relu + pairwise softmax -> d_out
// blockDim 242: kt = tid%121 (pair kt -> cols 2kt,2kt+1), rg = tid/121, 8 rows/thread
__global__ void k_gemm242f(const float* __restrict__ A, const float* __restrict__ W,
                           const float* __restrict__ bias, float* __restrict__ out, int N){
  const int K = 242, F = 64;
  int kt = threadIdx.x % 121;
  int rg = threadIdx.x / 121;
  int row0 = (blockIdx.x*2 + rg)*8;
  if (row0 >= N) return;
  int c0 = kt*2;
  ull acc[8];
  #pragma unroll
  for (int r=0;r<8;++r) acc[r]=0ull;
  int rr[8];
  #pragma unroll
  for (int r=0;r<8;++r) rr[r] = min(row0+r, N-1);

  for (int f=0; f<F; f+=4){
    ull w0 = *(const ull*)(W + (size_t)(f+0)*K + c0);
    ull w1 = *(const ull*)(W + (size_t)(f+1)*K + c0);
    ull w2 = *(const ull*)(W + (size_t)(f+2)*K + c0);
    ull w3 = *(const ull*)(W + (size_t)(f+3)*K + c0);
    #pragma unroll
    for (int r=0; r<8; ++r){
      float4 a = *(const float4*)(A + (size_t)rr[r]*F + f);
      acc[r] = ffma2(pack2(a.x,a.x), w0, acc[r]);
      acc[r] = ffma2(pack2(a.y,a.y), w1, acc[r]);
      acc[r] = ffma2(pack2(a.z,a.z), w2, acc[r]);
      acc[r] = ffma2(pack2(a.w,a.w), w3, acc[r]);
    }
  }
  float2 bb = *(const float2*)(bias + c0);
  #pragma unroll
  for (int r=0; r<8; ++r){
    if (row0+r < N){
      float2 v = unpack2(acc[r]);
      float v0 = fmaxf(v.x + bb.x, 0.f);
      float v1 = fmaxf(v.y + bb.y, 0.f);
      float m = fmaxf(v0, v1);
      float e0 = __expf(v0 - m), e1 = __expf(v1 - m);
      float rcp = 1.f / (e0 + e1);
      float2 o; o.x = e0*rcp; o.y = e1*rcp;
      *(float2*)(out + (size_t)(row0+r)*K + c0) = o;
    }
  }
}

// ---------------- host side ----------------
struct Scratch {
  float *xw, *h0, *h1, *as, *ad, *v;
  int *deg, *rowptr, *cursor, *esrc;
};

extern "C" void kernel_launch(void* const* d_in, const int* in_sizes, int n_in,
                              void* d_out, int out_size){
  const float* x  = (const float*)d_in[0];
  const int*   ei = (const int*)d_in[1];          // int32
  const float *W1=(const float*)d_in[2],  *a1s=(const float*)d_in[3],  *a1d=(const float*)d_in[4],  *b1=(const float*)d_in[5];
  const float *W2=(const float*)d_in[6],  *a2s=(const float*)d_in[7],  *a2d=(const float*)d_in[8],  *b2=(const float*)d_in[9];
  const float *W3=(const float*)d_in[10], *a3s=(const float*)d_in[11], *a3d=(const float*)d_in[12], *b3=(const float*)d_in[13];
  int N = in_sizes[0] / 128;
  int E = in_sizes[1] / 2;
  const int* src = ei;
  const int* dst = ei + E;

  Scratch S;
  cudaGetSymbolAddress((void**)&S.xw,     g_xw);
  cudaGetSymbolAddress((void**)&S.h0,     g_h0);
  cudaGetSymbolAddress((void**)&S.h1,     g_h1);
  cudaGetSymbolAddress((void**)&S.as,     g_as);
  cudaGetSymbolAddress((void**)&S.ad,     g_ad);
  cudaGetSymbolAddress((void**)&S.v,      g_v);
  cudaGetSymbolAddress((void**)&S.deg,    g_deg);
  cudaGetSymbolAddress((void**)&S.rowptr, g_rowptr);
  cudaGetSymbolAddress((void**)&S.cursor, g_cursor);
  cudaGetSymbolAddress((void**)&S.esrc,   g_esrc);

  const int B = 256;
  // CSR build (dst-sorted), once per call
  cudaMemsetAsync(S.deg, 0, (size_t)N*sizeof(int));
  k_hist<<<CDIV(E,B), B>>>(dst, E, S.deg);
  k_scan<<<1, 1024>>>(S.deg, S.rowptr, S.cursor, N);
  k_scatter<<<CDIV(E,B), B>>>(src, dst, E, S.cursor, S.esrc);

  // Layer 1: 128 -> 64, H=8, C=8
  k_gemm64<<<CDIV(N,64), 256>>>(x, W1, S.xw, N, 128);
  k_node_prep<<<CDIV(N*8,B), B>>>(S.xw, a1s, a1d, N, 8, 8, S.as, S.ad);
  k_aggr8<<<(unsigned)CDIV((long long)N*32,B), B>>>(S.rowptr, S.esrc, S.as, S.ad, S.xw, b1, S.h0, N);

  // Layer 2: 64 -> 64, H=8, C=8
  k_gemm64<<<CDIV(N,64), 256>>>(S.h0, W2, S.xw, N, 64);
  k_node_prep<<<CDIV(N*8,B), B>>>(S.xw, a2s, a2d, N, 8, 8, S.as, S.ad);
  k_aggr8<<<(unsigned)CDIV((long long)N*32,B), B>>>(S.rowptr, S.esrc, S.as, S.ad, S.xw, b2, S.h1, N);

  // Layer 3 (linearity): logits from h1 directly, aggregate 64-dim, project last
  k_prepvec<<<1, 64>>>(W3, a3s, a3d, S.v);
  k_dot64<<<(unsigned)CDIV((long long)N*32,B), B>>>(S.h1, S.v, S.as, S.ad, N);
  k_aggr64<<<(unsigned)CDIV((long long)N*32,B), B>>>(S.rowptr, S.esrc, S.as, S.ad, S.h1, S.xw, N);
  k_gemm242f<<<CDIV(N,16), 242>>>(S.xw, W3, b3, (float*)d_out, N);
}

// round 11
// speedup vs baseline: 2.4606x; 1.2689x over previous
#include <cuda_runtime.h>

#define CDIV(a,b) (((a)+(b)-1)/(b))
typedef unsigned long long ull;

static const int NMAX = 50000;
static const int EMAX = 800000;

// Scratch (device globals — no allocation allowed)
__device__ __align__(16) float g_xw  [(size_t)NMAX*242];
__device__ __align__(16) float g_h0  [(size_t)NMAX*64];
__device__ __align__(16) float g_h1  [(size_t)NMAX*64];
__device__ __align__(16) float g_as  [NMAX*8];
__device__ __align__(16) float g_ad  [NMAX*8];
__device__ __align__(16) float g_as3 [NMAX];
__device__ __align__(16) float g_ad3 [NMAX];
__device__ __align__(16) float g_v   [128];        // vsrc[64], vdst[64] for layer 3
__device__ int g_deg   [NMAX];
__device__ int g_rowptr[NMAX+1];
__device__ int g_cursor[NMAX];
__device__ int g_esrc  [EMAX];
__device__ int g_bsum  [256];
__device__ int g_boff  [256];

__device__ __forceinline__ float lrelu(float x){ return x > 0.f ? x : 0.2f*x; }

// ---- f32x2 packed helpers (FFMA2 path, sm_100+) ----
__device__ __forceinline__ ull pack2(float x, float y){
  ull d; asm("mov.b64 %0, {%1,%2};" : "=l"(d) : "f"(x), "f"(y)); return d;
}
__device__ __forceinline__ ull ffma2(ull a, ull b, ull c){
  ull r; asm("fma.rn.f32x2 %0, %1, %2, %3;" : "=l"(r) : "l"(a), "l"(b), "l"(c)); return r;
}
__device__ __forceinline__ float2 unpack2(ull d){
  float2 v; asm("mov.b64 {%0,%1}, %2;" : "=f"(v.x), "=f"(v.y) : "l"(d)); return v;
}

// ---------------- CSR build ----------------
__global__ void k_hist(const int* __restrict__ dst, int E, int* __restrict__ deg){
  int t = blockIdx.x*blockDim.x + threadIdx.x;
  if (t < E) atomicAdd(&deg[dst[t]], 1);
}

// scan stage 1: per-256-block sums
__global__ void k_scan1(const int* __restrict__ deg, int* __restrict__ bsum, int N){
  __shared__ int sm[256];
  int i = blockIdx.x*256 + threadIdx.x;
  sm[threadIdx.x] = (i < N) ? deg[i] : 0;
  __syncthreads();
  for (int off = 128; off; off >>= 1){
    if (threadIdx.x < off) sm[threadIdx.x] += sm[threadIdx.x + off];
    __syncthreads();
  }
  if (threadIdx.x == 0) bsum[blockIdx.x] = sm[0];
}

// scan stage 2: exclusive scan of block sums (NB <= 256), total -> rowptr[N]
__global__ void k_scan2(const int* __restrict__ bsum, int* __restrict__ boff,
                        int* __restrict__ rowptr, int NB, int N){
  __shared__ int sm[256];
  int tid = threadIdx.x;
  int v = (tid < NB) ? bsum[tid] : 0;
  sm[tid] = v;
  __syncthreads();
  for (int off = 1; off < 256; off <<= 1){
    int t = (tid >= off) ? sm[tid-off] : 0;
    __syncthreads();
    sm[tid] += t;
    __syncthreads();
  }
  if (tid < NB) boff[tid] = sm[tid] - v;
  if (tid == 255) rowptr[N] = sm[255];
}

// scan stage 3: local exclusive scan + block offset
__global__ void k_scan3(const int* __restrict__ deg, const int* __restrict__ boff,
                        int* __restrict__ rowptr, int* __restrict__ cursor, int N){
  __shared__ int sm[256];
  int tid = threadIdx.x;
  int i = blockIdx.x*256 + tid;
  int v = (i < N) ? deg[i] : 0;
  sm[tid] = v;
  __syncthreads();
  for (int off = 1; off < 256; off <<= 1){
    int t = (tid >= off) ? sm[tid-off] : 0;
    __syncthreads();
    sm[tid] += t;
    __syncthreads();
  }
  if (i < N){
    int ex = boff[blockIdx.x] + sm[tid] - v;
    rowptr[i] = ex; cursor[i] = ex;
  }
}

__global__ void k_scatter(const int* __restrict__ src, const int* __restrict__ dst, int E,
                          int* __restrict__ cursor, int* __restrict__ esrc){
  int t = blockIdx.x*blockDim.x + threadIdx.x;
  if (t >= E) return;
  int p = atomicAdd(&cursor[dst[t]], 1);
  esrc[p] = src[t];
}

// ---- GEMM K=64 (layers 1/2): SMEM W, f32x2, 8 rows x 4 cols / thread,
//      fused per-(row,head) logit epilogue (as/ad) ----
// blockDim 256: kt = tid&15 (4 cols), rg = tid>>4 -> 128 rows/block
__global__ __launch_bounds__(256) void k_gemm64f(
    const float* __restrict__ A, const float* __restrict__ W,
    const float* __restrict__ asrc, const float* __restrict__ adst,
    float* __restrict__ O, float* __restrict__ as, float* __restrict__ ad,
    int N, int F){
  const int K = 64;
  __shared__ float sW[128*64];          // up to F=128
  for (int i = threadIdx.x; i < (F*K)/4; i += 256)
    ((float4*)sW)[i] = ((const float4*)W)[i];
  __syncthreads();

  int kt = threadIdx.x & 15;
  int rg = threadIdx.x >> 4;
  int row0 = (blockIdx.x*16 + rg)*8;
  int c0 = kt*4;
  ull acc[8][2];
  #pragma unroll
  for (int r=0;r<8;++r){ acc[r][0]=0ull; acc[r][1]=0ull; }
  int rr[8];
  #pragma unroll
  for (int r=0;r<8;++r) rr[r] = min(row0+r, N-1);

  for (int f=0; f<F; f+=4){
    ulonglong2 w[4];
    #pragma unroll
    for (int u=0; u<4; ++u)
      w[u] = *(const ulonglong2*)(sW + (f+u)*K + c0);
    #pragma unroll
    for (int r=0; r<8; ++r){
      float4 a = *(const float4*)(A + (size_t)rr[r]*F + f);
      ull ax = pack2(a.x,a.x), ay = pack2(a.y,a.y), az = pack2(a.z,a.z), aw = pack2(a.w,a.w);
      acc[r][0] = ffma2(ax, w[0].x, acc[r][0]); acc[r][1] = ffma2(ax, w[0].y, acc[r][1]);
      acc[r][0] = ffma2(ay, w[1].x, acc[r][0]); acc[r][1] = ffma2(ay, w[1].y, acc[r][1]);
      acc[r][0] = ffma2(az, w[2].x, acc[r][0]); acc[r][1] = ffma2(az, w[2].y, acc[r][1]);
      acc[r][0] = ffma2(aw, w[3].x, acc[r][0]); acc[r][1] = ffma2(aw, w[3].y, acc[r][1]);
    }
  }

  // epilogue: store O; compute per-head logits (cols c0..c0+3 = half of head kt>>1)
  float4 av = *(const float4*)(asrc + c0);
  float4 dv = *(const float4*)(adst + c0);
  int h = kt >> 1;
  #pragma unroll
  for (int r=0; r<8; ++r){
    float2 lo = unpack2(acc[r][0]), hi = unpack2(acc[r][1]);
    bool ok = (row0 + r) < N;
    if (ok){
      float4 o; o.x=lo.x; o.y=lo.y; o.z=hi.x; o.w=hi.y;
      *(float4*)(O + (size_t)(row0+r)*K + c0) = o;
    }
    float s = lo.x*av.x + lo.y*av.y + hi.x*av.z + hi.y*av.w;
    float d = lo.x*dv.x + lo.y*dv.y + hi.x*dv.z + hi.y*dv.w;
    s += __shfl_xor_sync(0xffffffffu, s, 1);
    d += __shfl_xor_sync(0xffffffffu, d, 1);
    if (ok && !(kt & 1)){
      as[(size_t)(row0+r)*8 + h] = s;
      ad[(size_t)(row0+r)*8 + h] = d;
    }
  }
}

// -------- fused aggregation, H=8 C=8 (F=64): warp per dst node.
//          Optional fused layer-3 logit dots (v3 != null) --------
__global__ void k_aggr8(const int* __restrict__ rowptr, const int* __restrict__ esrc,
                        const float* __restrict__ as, const float* __restrict__ ad,
                        const float* __restrict__ xw, const float* __restrict__ bias,
                        float* __restrict__ out, int N,
                        const float* __restrict__ v3,
                        float* __restrict__ as3, float* __restrict__ ad3){
  int w = (int)(((long long)blockIdx.x*blockDim.x + threadIdx.x) >> 5);
  int lane = threadIdx.x & 31;
  if (w >= N) return;
  int h = lane >> 2;
  float adv = __ldg(&ad[w*8+h]);
  const float2* xw2 = (const float2*)xw;

  // self-loop
  float p = __expf(lrelu(__ldg(&as[w*8+h]) + adv));
  float2 xv = xw2[(size_t)w*32 + lane];
  float accx = p*xv.x, accy = p*xv.y, den = p;

  int k  = rowptr[w];
  int ke = rowptr[w+1];
  for (; k+1 < ke; k += 2){
    int s0 = __ldg(&esrc[k]);
    int s1 = __ldg(&esrc[k+1]);
    float p0 = __expf(lrelu(__ldg(&as[s0*8+h]) + adv));
    float p1 = __expf(lrelu(__ldg(&as[s1*8+h]) + adv));
    float2 v0 = xw2[(size_t)s0*32 + lane];
    float2 v1 = xw2[(size_t)s1*32 + lane];
    accx = fmaf(p0, v0.x, accx); accy = fmaf(p0, v0.y, accy);
    accx = fmaf(p1, v1.x, accx); accy = fmaf(p1, v1.y, accy);
    den += p0 + p1;
  }
  if (k < ke){
    int s0 = __ldg(&esrc[k]);
    float p0 = __expf(lrelu(__ldg(&as[s0*8+h]) + adv));
    float2 v0 = xw2[(size_t)s0*32 + lane];
    accx = fmaf(p0, v0.x, accx); accy = fmaf(p0, v0.y, accy);
    den += p0;
  }
  float inv = 1.f / (den + 1e-16f);
  float2 bv = ((const float2*)bias)[lane];
  float2 o;
  o.x = fmaxf(fmaf(accx, inv, bv.x), 0.f);
  o.y = fmaxf(fmaf(accy, inv, bv.y), 0.f);
  ((float2*)out)[(size_t)w*32 + lane] = o;

  if (v3){
    // layer-3 logits: as3[w] = out_row . v3[0:64], ad3 with v3[64:128]
    float2 vs = ((const float2*)v3)[lane];
    float2 vd = ((const float2*)v3)[32 + lane];
    float s = o.x*vs.x + o.y*vs.y;
    float d = o.x*vd.x + o.y*vd.y;
    #pragma unroll
    for (int off=16; off; off>>=1){
      s += __shfl_xor_sync(0xffffffffu, s, off);
      d += __shfl_xor_sync(0xffffffffu, d, off);
    }
    if (lane == 0){ as3[w] = s; ad3[w] = d; }
  }
}

// ======== Layer 3 (linearity: aggregate h1 first, project after) ========

// v[0:64] = W3 @ a3s, v[64:128] = W3 @ a3d   (warp per row)
__global__ void k_prepvec(const float* __restrict__ W3, const float* __restrict__ a3s,
                          const float* __restrict__ a3d, float* __restrict__ v){
  int w = (blockIdx.x*blockDim.x + threadIdx.x) >> 5;
  int lane = threadIdx.x & 31;
  if (w >= 64) return;
  const float* row = W3 + (size_t)w*242;
  float s=0.f, d=0.f;
  for (int c=lane; c<242; c+=32){ float t=row[c]; s=fmaf(t,a3s[c],s); d=fmaf(t,a3d[c],d); }
  #pragma unroll
  for (int o=16; o; o>>=1){
    s += __shfl_xor_sync(0xffffffffu, s, o);
    d += __shfl_xor_sync(0xffffffffu, d, o);
  }
  if (lane == 0){ v[w]=s; v[64+w]=d; }
}

// 64-dim aggregation with softmax weights, normalized output (warp per node)
__global__ void k_aggr64(const int* __restrict__ rowptr, const int* __restrict__ esrc,
                         const float* __restrict__ as, const float* __restrict__ ad,
                         const float* __restrict__ h, float* __restrict__ agg, int N){
  int w = (int)(((long long)blockIdx.x*blockDim.x + threadIdx.x) >> 5);
  int lane = threadIdx.x & 31;
  if (w >= N) return;
  float adv = __ldg(&ad[w]);
  const float2* h2 = (const float2*)h;

  // self-loop
  float p = __expf(lrelu(__ldg(&as[w]) + adv));
  float2 xv = h2[(size_t)w*32 + lane];
  float accx = p*xv.x, accy = p*xv.y, den = p;

  int k  = rowptr[w];
  int ke = rowptr[w+1];
  for (; k+1 < ke; k += 2){
    int s0 = __ldg(&esrc[k]);
    int s1 = __ldg(&esrc[k+1]);
    float p0 = __expf(lrelu(__ldg(&as[s0]) + adv));
    float p1 = __expf(lrelu(__ldg(&as[s1]) + adv));
    float2 v0 = h2[(size_t)s0*32 + lane];
    float2 v1 = h2[(size_t)s1*32 + lane];
    accx = fmaf(p0, v0.x, accx); accy = fmaf(p0, v0.y, accy);
    accx = fmaf(p1, v1.x, accx); accy = fmaf(p1, v1.y, accy);
    den += p0 + p1;
  }
  if (k < ke){
    int s0 = __ldg(&esrc[k]);
    float p0 = __expf(lrelu(__ldg(&as[s0]) + adv));
    float2 v0 = h2[(size_t)s0*32 + lane];
    accx = fmaf(p0, v0.x, accx); accy = fmaf(p0, v0.y, accy);
    den += p0;
  }
  float inv = 1.f / (den + 1e-16f);
  float2 o; o.x = accx*inv; o.y = accy*inv;
  ((float2*)agg)[(size_t)w*32 + lane] = o;
}

// final GEMM [N,64]@[64,242] + bias + relu + pairwise softmax -> d_out
// blockDim 242: kt = tid%121 (pair kt -> cols 2kt,2kt+1), rg = tid/121, 8 rows/thread
__global__ void k_gemm242f(const float* __restrict__ A, const float* __restrict__ W,
                           const float* __restrict__ bias, float* __restrict__ out, int N){
  const int K = 242, F = 64;
  int kt = threadIdx.x % 121;
  int rg = threadIdx.x / 121;
  int row0 = (blockIdx.x*2 + rg)*8;
  if (row0 >= N) return;
  int c0 = kt*2;
  ull acc[8];
  #pragma unroll
  for (int r=0;r<8;++r) acc[r]=0ull;
  int rr[8];
  #pragma unroll
  for (int r=0;r<8;++r) rr[r] = min(row0+r, N-1);

  for (int f=0; f<F; f+=4){
    ull w0 = *(const ull*)(W + (size_t)(f+0)*K + c0);
    ull w1 = *(const ull*)(W + (size_t)(f+1)*K + c0);
    ull w2 = *(const ull*)(W + (size_t)(f+2)*K + c0);
    ull w3 = *(const ull*)(W + (size_t)(f+3)*K + c0);
    #pragma unroll
    for (int r=0; r<8; ++r){
      float4 a = *(const float4*)(A + (size_t)rr[r]*F + f);
      acc[r] = ffma2(pack2(a.x,a.x), w0, acc[r]);
      acc[r] = ffma2(pack2(a.y,a.y), w1, acc[r]);
      acc[r] = ffma2(pack2(a.z,a.z), w2, acc[r]);
      acc[r] = ffma2(pack2(a.w,a.w), w3, acc[r]);
    }
  }
  float2 bb = *(const float2*)(bias + c0);
  #pragma unroll
  for (int r=0; r<8; ++r){
    if (row0+r < N){
      float2 v = unpack2(acc[r]);
      float v0 = fmaxf(v.x + bb.x, 0.f);
      float v1 = fmaxf(v.y + bb.y, 0.f);
      float m = fmaxf(v0, v1);
      float e0 = __expf(v0 - m), e1 = __expf(v1 - m);
      float rcp = 1.f / (e0 + e1);
      float2 o; o.x = e0*rcp; o.y = e1*rcp;
      *(float2*)(out + (size_t)(row0+r)*K + c0) = o;
    }
  }
}

// ---------------- host side ----------------
struct Scratch {
  float *xw, *h0, *h1, *as, *ad, *as3, *ad3, *v;
  int *deg, *rowptr, *cursor, *esrc, *bsum, *boff;
};

extern "C" void kernel_launch(void* const* d_in, const int* in_sizes, int n_in,
                              void* d_out, int out_size){
  const float* x  = (const float*)d_in[0];
  const int*   ei = (const int*)d_in[1];          // int32
  const float *W1=(const float*)d_in[2],  *a1s=(const float*)d_in[3],  *a1d=(const float*)d_in[4],  *b1=(const float*)d_in[5];
  const float *W2=(const float*)d_in[6],  *a2s=(const float*)d_in[7],  *a2d=(const float*)d_in[8],  *b2=(const float*)d_in[9];
  const float *W3=(const float*)d_in[10], *a3s=(const float*)d_in[11], *a3d=(const float*)d_in[12], *b3=(const float*)d_in[13];
  int N = in_sizes[0] / 128;
  int E = in_sizes[1] / 2;
  const int* src = ei;
  const int* dst = ei + E;

  Scratch S;
  cudaGetSymbolAddress((void**)&S.xw,     g_xw);
  cudaGetSymbolAddress((void**)&S.h0,     g_h0);
  cudaGetSymbolAddress((void**)&S.h1,     g_h1);
  cudaGetSymbolAddress((void**)&S.as,     g_as);
  cudaGetSymbolAddress((void**)&S.ad,     g_ad);
  cudaGetSymbolAddress((void**)&S.as3,    g_as3);
  cudaGetSymbolAddress((void**)&S.ad3,    g_ad3);
  cudaGetSymbolAddress((void**)&S.v,      g_v);
  cudaGetSymbolAddress((void**)&S.deg,    g_deg);
  cudaGetSymbolAddress((void**)&S.rowptr, g_rowptr);
  cudaGetSymbolAddress((void**)&S.cursor, g_cursor);
  cudaGetSymbolAddress((void**)&S.esrc,   g_esrc);
  cudaGetSymbolAddress((void**)&S.bsum,   g_bsum);
  cudaGetSymbolAddress((void**)&S.boff,   g_boff);

  const int B = 256;
  int NB = CDIV(N, 256);    // <= 256 for N <= 65536
  // CSR build (dst-sorted), once per call
  cudaMemsetAsync(S.deg, 0, (size_t)N*sizeof(int));
  k_hist<<<CDIV(E,B), B>>>(dst, E, S.deg);
  k_scan1<<<NB, 256>>>(S.deg, S.bsum, N);
  k_scan2<<<1, 256>>>(S.bsum, S.boff, S.rowptr, NB, N);
  k_scan3<<<NB, 256>>>(S.deg, S.boff, S.rowptr, S.cursor, N);
  k_scatter<<<CDIV(E,B), B>>>(src, dst, E, S.cursor, S.esrc);
  k_prepvec<<<8, 256>>>(W3, a3s, a3d, S.v);

  // Layer 1: 128 -> 64, H=8, C=8 (GEMM + fused logits)
  k_gemm64f<<<CDIV(N,128), 256>>>(x, W1, a1s, a1d, S.xw, S.as, S.ad, N, 128);
  k_aggr8<<<(unsigned)CDIV((long long)N*32,B), B>>>(S.rowptr, S.esrc, S.as, S.ad, S.xw, b1,
                                                    S.h0, N, nullptr, nullptr, nullptr);

  // Layer 2: 64 -> 64, H=8, C=8 (aggr fuses layer-3 logit dots)
  k_gemm64f<<<CDIV(N,128), 256>>>(S.h0, W2, a2s, a2d, S.xw, S.as, S.ad, N, 64);
  k_aggr8<<<(unsigned)CDIV((long long)N*32,B), B>>>(S.rowptr, S.esrc, S.as, S.ad, S.xw, b2,
                                                    S.h1, N, S.v, S.as3, S.ad3);

  // Layer 3 (linearity): aggregate 64-dim, project last (fused bias/relu/softmax)
  k_aggr64<<<(unsigned)CDIV((long long)N*32,B), B>>>(S.rowptr, S.esrc, S.as3, S.ad3, S.h1, S.xw, N);
  k_gemm242f<<<CDIV(N,16), 242>>>(S.xw, W3, b3, (float*)d_out, N);
}

// round 14
// speedup vs baseline: 2.6431x; 1.0742x over previous
#include <cuda_runtime.h>

#define CDIV(a,b) (((a)+(b)-1)/(b))
typedef unsigned long long ull;

static const int NMAX = 50000;
static const int EMAX = 800000;

// Scratch (device globals — no allocation allowed)
__device__ __align__(16) float g_xw  [(size_t)NMAX*242];
__device__ __align__(16) float g_h0  [(size_t)NMAX*64];
__device__ __align__(16) float g_h1  [(size_t)NMAX*64];
__device__ __align__(16) float g_as  [NMAX*8];
__device__ __align__(16) float g_ad  [NMAX*8];
__device__ __align__(16) float g_as3 [NMAX];
__device__ __align__(16) float g_ad3 [NMAX];
__device__ __align__(16) float g_v   [128];        // vsrc[64], vdst[64] for layer 3
__device__ int g_deg   [NMAX];
__device__ int g_rowptr[NMAX+1];
__device__ int g_cursor[NMAX];
__device__ int g_esrc  [EMAX];
__device__ int g_bsum  [256];
__device__ int g_boff  [256];

__device__ __forceinline__ float lrelu(float x){ return x > 0.f ? x : 0.2f*x; }

// ---- f32x2 packed helpers (FFMA2 path, sm_100+) ----
__device__ __forceinline__ ull pack2(float x, float y){
  ull d; asm("mov.b64 %0, {%1,%2};" : "=l"(d) : "f"(x), "f"(y)); return d;
}
__device__ __forceinline__ ull ffma2(ull a, ull b, ull c){
  ull r; asm("fma.rn.f32x2 %0, %1, %2, %3;" : "=l"(r) : "l"(a), "l"(b), "l"(c)); return r;
}
__device__ __forceinline__ float2 unpack2(ull d){
  float2 v; asm("mov.b64 {%0,%1}, %2;" : "=f"(v.x), "=f"(v.y) : "l"(d)); return v;
}

// ---------------- CSR build ----------------
__global__ void k_hist(const int* __restrict__ dst, int E, int* __restrict__ deg){
  int t = blockIdx.x*blockDim.x + threadIdx.x;
  if (t < E) atomicAdd(&deg[dst[t]], 1);
}

__global__ void k_scan1(const int* __restrict__ deg, int* __restrict__ bsum, int N){
  __shared__ int sm[256];
  int i = blockIdx.x*256 + threadIdx.x;
  sm[threadIdx.x] = (i < N) ? deg[i] : 0;
  __syncthreads();
  for (int off = 128; off; off >>= 1){
    if (threadIdx.x < off) sm[threadIdx.x] += sm[threadIdx.x + off];
    __syncthreads();
  }
  if (threadIdx.x == 0) bsum[blockIdx.x] = sm[0];
}

__global__ void k_scan2(const int* __restrict__ bsum, int* __restrict__ boff,
                        int* __restrict__ rowptr, int NB, int N){
  __shared__ int sm[256];
  int tid = threadIdx.x;
  int v = (tid < NB) ? bsum[tid] : 0;
  sm[tid] = v;
  __syncthreads();
  for (int off = 1; off < 256; off <<= 1){
    int t = (tid >= off) ? sm[tid-off] : 0;
    __syncthreads();
    sm[tid] += t;
    __syncthreads();
  }
  if (tid < NB) boff[tid] = sm[tid] - v;
  if (tid == 255) rowptr[N] = sm[255];
}

__global__ void k_scan3(const int* __restrict__ deg, const int* __restrict__ boff,
                        int* __restrict__ rowptr, int* __restrict__ cursor, int N){
  __shared__ int sm[256];
  int tid = threadIdx.x;
  int i = blockIdx.x*256 + tid;
  int v = (i < N) ? deg[i] : 0;
  sm[tid] = v;
  __syncthreads();
  for (int off = 1; off < 256; off <<= 1){
    int t = (tid >= off) ? sm[tid-off] : 0;
    __syncthreads();
    sm[tid] += t;
    __syncthreads();
  }
  if (i < N){
    int ex = boff[blockIdx.x] + sm[tid] - v;
    rowptr[i] = ex; cursor[i] = ex;
  }
}

__global__ void k_scatter(const int* __restrict__ src, const int* __restrict__ dst, int E,
                          int* __restrict__ cursor, int* __restrict__ esrc){
  int t = blockIdx.x*blockDim.x + threadIdx.x;
  if (t >= E) return;
  int p = atomicAdd(&cursor[dst[t]], 1);
  esrc[p] = src[t];
}

// ---- GEMM K=64 (layers 1/2): SMEM W, f32x2, 8 rows x 4 cols / thread,
//      fused per-(row,head) logit epilogue (as/ad) ----
__global__ __launch_bounds__(256) void k_gemm64f(
    const float* __restrict__ A, const float* __restrict__ W,
    const float* __restrict__ asrc, const float* __restrict__ adst,
    float* __restrict__ O, float* __restrict__ as, float* __restrict__ ad,
    int N, int F){
  const int K = 64;
  __shared__ float sW[128*64];          // up to F=128
  for (int i = threadIdx.x; i < (F*K)/4; i += 256)
    ((float4*)sW)[i] = ((const float4*)W)[i];
  __syncthreads();

  int kt = threadIdx.x & 15;
  int rg = threadIdx.x >> 4;
  int row0 = (blockIdx.x*16 + rg)*8;
  int c0 = kt*4;
  ull acc[8][2];
  #pragma unroll
  for (int r=0;r<8;++r){ acc[r][0]=0ull; acc[r][1]=0ull; }
  int rr[8];
  #pragma unroll
  for (int r=0;r<8;++r) rr[r] = min(row0+r, N-1);

  for (int f=0; f<F; f+=4){
    ulonglong2 w[4];
    #pragma unroll
    for (int u=0; u<4; ++u)
      w[u] = *(const ulonglong2*)(sW + (f+u)*K + c0);
    #pragma unroll
    for (int r=0; r<8; ++r){
      float4 a = *(const float4*)(A + (size_t)rr[r]*F + f);
      ull ax = pack2(a.x,a.x), ay = pack2(a.y,a.y), az = pack2(a.z,a.z), aw = pack2(a.w,a.w);
      acc[r][0] = ffma2(ax, w[0].x, acc[r][0]); acc[r][1] = ffma2(ax, w[0].y, acc[r][1]);
      acc[r][0] = ffma2(ay, w[1].x, acc[r][0]); acc[r][1] = ffma2(ay, w[1].y, acc[r][1]);
      acc[r][0] = ffma2(az, w[2].x, acc[r][0]); acc[r][1] = ffma2(az, w[2].y, acc[r][1]);
      acc[r][0] = ffma2(aw, w[3].x, acc[r][0]); acc[r][1] = ffma2(aw, w[3].y, acc[r][1]);
    }
  }

  float4 av = *(const float4*)(asrc + c0);
  float4 dv = *(const float4*)(adst + c0);
  int h = kt >> 1;
  #pragma unroll
  for (int r=0; r<8; ++r){
    float2 lo = unpack2(acc[r][0]), hi = unpack2(acc[r][1]);
    bool ok = (row0 + r) < N;
    if (ok){
      float4 o; o.x=lo.x; o.y=lo.y; o.z=hi.x; o.w=hi.y;
      *(float4*)(O + (size_t)(row0+r)*K + c0) = o;
    }
    float s = lo.x*av.x + lo.y*av.y + hi.x*av.z + hi.y*av.w;
    float d = lo.x*dv.x + lo.y*dv.y + hi.x*dv.z + hi.y*dv.w;
    s += __shfl_xor_sync(0xffffffffu, s, 1);
    d += __shfl_xor_sync(0xffffffffu, d, 1);
    if (ok && !(kt & 1)){
      as[(size_t)(row0+r)*8 + h] = s;
      ad[(size_t)(row0+r)*8 + h] = d;
    }
  }
}

// -------- fused aggregation, H=8 C=8 (F=64): warp per dst node, 4-edge unroll.
//          Optional fused layer-3 logit dots (v3 != null) --------
__global__ void k_aggr8(const int* __restrict__ rowptr, const int* __restrict__ esrc,
                        const float* __restrict__ as, const float* __restrict__ ad,
                        const float* __restrict__ xw, const float* __restrict__ bias,
                        float* __restrict__ out, int N,
                        const float* __restrict__ v3,
                        float* __restrict__ as3, float* __restrict__ ad3){
  int w = (int)(((long long)blockIdx.x*blockDim.x + threadIdx.x) >> 5);
  int lane = threadIdx.x & 31;
  if (w >= N) return;
  int h = lane >> 2;
  float adv = __ldg(&ad[w*8+h]);
  const float2* xw2 = (const float2*)xw;

  // self-loop
  float p = __expf(lrelu(__ldg(&as[w*8+h]) + adv));
  float2 xv = xw2[(size_t)w*32 + lane];
  float accx = p*xv.x, accy = p*xv.y, den = p;

  int k  = rowptr[w];
  int ke = rowptr[w+1];
  for (; k+4 <= ke; k += 4){
    int s0 = __ldg(&esrc[k]);
    int s1 = __ldg(&esrc[k+1]);
    int s2 = __ldg(&esrc[k+2]);
    int s3 = __ldg(&esrc[k+3]);
    float e0 = __ldg(&as[s0*8+h]);
    float e1 = __ldg(&as[s1*8+h]);
    float e2 = __ldg(&as[s2*8+h]);
    float e3 = __ldg(&as[s3*8+h]);
    float2 v0 = xw2[(size_t)s0*32 + lane];
    float2 v1 = xw2[(size_t)s1*32 + lane];
    float2 v2 = xw2[(size_t)s2*32 + lane];
    float2 v3v= xw2[(size_t)s3*32 + lane];
    float p0 = __expf(lrelu(e0 + adv));
    float p1 = __expf(lrelu(e1 + adv));
    float p2 = __expf(lrelu(e2 + adv));
    float p3 = __expf(lrelu(e3 + adv));
    accx = fmaf(p0, v0.x, accx); accy = fmaf(p0, v0.y, accy);
    accx = fmaf(p1, v1.x, accx); accy = fmaf(p1, v1.y, accy);
    accx = fmaf(p2, v2.x, accx); accy = fmaf(p2, v2.y, accy);
    accx = fmaf(p3, v3v.x,accx); accy = fmaf(p3, v3v.y,accy);
    den += (p0 + p1) + (p2 + p3);
  }
  for (; k < ke; ++k){
    int s0 = __ldg(&esrc[k]);
    float p0 = __expf(lrelu(__ldg(&as[s0*8+h]) + adv));
    float2 v0 = xw2[(size_t)s0*32 + lane];
    accx = fmaf(p0, v0.x, accx); accy = fmaf(p0, v0.y, accy);
    den += p0;
  }
  float inv = 1.f / (den + 1e-16f);
  float2 bv = ((const float2*)bias)[lane];
  float2 o;
  o.x = fmaxf(fmaf(accx, inv, bv.x), 0.f);
  o.y = fmaxf(fmaf(accy, inv, bv.y), 0.f);
  ((float2*)out)[(size_t)w*32 + lane] = o;

  if (v3){
    float2 vs = ((const float2*)v3)[lane];
    float2 vd = ((const float2*)v3)[32 + lane];
    float s = o.x*vs.x + o.y*vs.y;
    float d = o.x*vd.x + o.y*vd.y;
    #pragma unroll
    for (int off=16; off; off>>=1){
      s += __shfl_xor_sync(0xffffffffu, s, off);
      d += __shfl_xor_sync(0xffffffffu, d, off);
    }
    if (lane == 0){ as3[w] = s; ad3[w] = d; }
  }
}

// ======== Layer 3 (linearity: aggregate h1 first, project after) ========

__global__ void k_prepvec(const float* __restrict__ W3, const float* __restrict__ a3s,
                          const float* __restrict__ a3d, float* __restrict__ v){
  int w = (blockIdx.x*blockDim.x + threadIdx.x) >> 5;
  int lane = threadIdx.x & 31;
  if (w >= 64) return;
  const float* row = W3 + (size_t)w*242;
  float s=0.f, d=0.f;
  for (int c=lane; c<242; c+=32){ float t=row[c]; s=fmaf(t,a3s[c],s); d=fmaf(t,a3d[c],d); }
  #pragma unroll
  for (int o=16; o; o>>=1){
    s += __shfl_xor_sync(0xffffffffu, s, o);
    d += __shfl_xor_sync(0xffffffffu, d, o);
  }
  if (lane == 0){ v[w]=s; v[64+w]=d; }
}

// 64-dim aggregation with softmax weights, normalized output (warp per node, 4-edge unroll)
__global__ void k_aggr64(const int* __restrict__ rowptr, const int* __restrict__ esrc,
                         const float* __restrict__ as, const float* __restrict__ ad,
                         const float* __restrict__ h, float* __restrict__ agg, int N){
  int w = (int)(((long long)blockIdx.x*blockDim.x + threadIdx.x) >> 5);
  int lane = threadIdx.x & 31;
  if (w >= N) return;
  float adv = __ldg(&ad[w]);
  const float2* h2 = (const float2*)h;

  float p = __expf(lrelu(__ldg(&as[w]) + adv));
  float2 xv = h2[(size_t)w*32 + lane];
  float accx = p*xv.x, accy = p*xv.y, den = p;

  int k  = rowptr[w];
  int ke = rowptr[w+1];
  for (; k+4 <= ke; k += 4){
    int s0 = __ldg(&esrc[k]);
    int s1 = __ldg(&esrc[k+1]);
    int s2 = __ldg(&esrc[k+2]);
    int s3 = __ldg(&esrc[k+3]);
    float e0 = __ldg(&as[s0]);
    float e1 = __ldg(&as[s1]);
    float e2 = __ldg(&as[s2]);
    float e3 = __ldg(&as[s3]);
    float2 v0 = h2[(size_t)s0*32 + lane];
    float2 v1 = h2[(size_t)s1*32 + lane];
    float2 v2 = h2[(size_t)s2*32 + lane];
    float2 v3 = h2[(size_t)s3*32 + lane];
    float p0 = __expf(lrelu(e0 + adv));
    float p1 = __expf(lrelu(e1 + adv));
    float p2 = __expf(lrelu(e2 + adv));
    float p3 = __expf(lrelu(e3 + adv));
    accx = fmaf(p0, v0.x, accx); accy = fmaf(p0, v0.y, accy);
    accx = fmaf(p1, v1.x, accx); accy = fmaf(p1, v1.y, accy);
    accx = fmaf(p2, v2.x, accx); accy = fmaf(p2, v2.y, accy);
    accx = fmaf(p3, v3.x, accx); accy = fmaf(p3, v3.y, accy);
    den += (p0 + p1) + (p2 + p3);
  }
  for (; k < ke; ++k){
    int s0 = __ldg(&esrc[k]);
    float p0 = __expf(lrelu(__ldg(&as[s0]) + adv));
    float2 v0 = h2[(size_t)s0*32 + lane];
    accx = fmaf(p0, v0.x, accx); accy = fmaf(p0, v0.y, accy);
    den += p0;
  }
  float inv = 1.f / (den + 1e-16f);
  float2 o; o.x = accx*inv; o.y = accy*inv;
  ((float2*)agg)[(size_t)w*32 + lane] = o;
}

// final GEMM [N,64]@[64,242] + bias + relu + pairwise softmax -> d_out
__global__ void k_gemm242f(const float* __restrict__ A, const float* __restrict__ W,
                           const float* __restrict__ bias, float* __restrict__ out, int N){
  const int K = 242, F = 64;
  int kt = threadIdx.x % 121;
  int rg = threadIdx.x / 121;
  int row0 = (blockIdx.x*2 + rg)*8;
  if (row0 >= N) return;
  int c0 = kt*2;
  ull acc[8];
  #pragma unroll
  for (int r=0;r<8;++r) acc[r]=0ull;
  int rr[8];
  #pragma unroll
  for (int r=0;r<8;++r) rr[r] = min(row0+r, N-1);

  for (int f=0; f<F; f+=4){
    ull w0 = *(const ull*)(W + (size_t)(f+0)*K + c0);
    ull w1 = *(const ull*)(W + (size_t)(f+1)*K + c0);
    ull w2 = *(const ull*)(W + (size_t)(f+2)*K + c0);
    ull w3 = *(const ull*)(W + (size_t)(f+3)*K + c0);
    #pragma unroll
    for (int r=0; r<8; ++r){
      float4 a = *(const float4*)(A + (size_t)rr[r]*F + f);
      acc[r] = ffma2(pack2(a.x,a.x), w0, acc[r]);
      acc[r] = ffma2(pack2(a.y,a.y), w1, acc[r]);
      acc[r] = ffma2(pack2(a.z,a.z), w2, acc[r]);
      acc[r] = ffma2(pack2(a.w,a.w), w3, acc[r]);
    }
  }
  float2 bb = *(const float2*)(bias + c0);
  #pragma unroll
  for (int r=0; r<8; ++r){
    if (row0+r < N){
      float2 v = unpack2(acc[r]);
      float v0 = fmaxf(v.x + bb.x, 0.f);
      float v1 = fmaxf(v.y + bb.y, 0.f);
      float m = fmaxf(v0, v1);
      float e0 = __expf(v0 - m), e1 = __expf(v1 - m);
      float rcp = 1.f / (e0 + e1);
      float2 o; o.x = e0*rcp; o.y = e1*rcp;
      *(float2*)(out + (size_t)(row0+r)*K + c0) = o;
    }
  }
}

// ---------------- host side ----------------
struct Scratch {
  float *xw, *h0, *h1, *as, *ad, *as3, *ad3, *v;
  int *deg, *rowptr, *cursor, *esrc, *bsum, *boff;
};

extern "C" void kernel_launch(void* const* d_in, const int* in_sizes, int n_in,
                              void* d_out, int out_size){
  const float* x  = (const float*)d_in[0];
  const int*   ei = (const int*)d_in[1];          // int32
  const float *W1=(const float*)d_in[2],  *a1s=(const float*)d_in[3],  *a1d=(const float*)d_in[4],  *b1=(const float*)d_in[5];
  const float *W2=(const float*)d_in[6],  *a2s=(const float*)d_in[7],  *a2d=(const float*)d_in[8],  *b2=(const float*)d_in[9];
  const float *W3=(const float*)d_in[10], *a3s=(const float*)d_in[11], *a3d=(const float*)d_in[12], *b3=(const float*)d_in[13];
  int N = in_sizes[0] / 128;
  int E = in_sizes[1] / 2;
  const int* src = ei;
  const int* dst = ei + E;

  Scratch S;
  cudaGetSymbolAddress((void**)&S.xw,     g_xw);
  cudaGetSymbolAddress((void**)&S.h0,     g_h0);
  cudaGetSymbolAddress((void**)&S.h1,     g_h1);
  cudaGetSymbolAddress((void**)&S.as,     g_as);
  cudaGetSymbolAddress((void**)&S.ad,     g_ad);
  cudaGetSymbolAddress((void**)&S.as3,    g_as3);
  cudaGetSymbolAddress((void**)&S.ad3,    g_ad3);
  cudaGetSymbolAddress((void**)&S.v,      g_v);
  cudaGetSymbolAddress((void**)&S.deg,    g_deg);
  cudaGetSymbolAddress((void**)&S.rowptr, g_rowptr);
  cudaGetSymbolAddress((void**)&S.cursor, g_cursor);
  cudaGetSymbolAddress((void**)&S.esrc,   g_esrc);
  cudaGetSymbolAddress((void**)&S.bsum,   g_bsum);
  cudaGetSymbolAddress((void**)&S.boff,   g_boff);

  // one-time infra (host objects only; created on first, non-captured call)
  static cudaStream_t s2 = 0;
  static cudaEvent_t evFork = 0, evJoin = 0;
  if (!s2){
    if (cudaStreamCreateWithFlags(&s2, cudaStreamNonBlocking) != cudaSuccess) s2 = 0;
    if (s2){
      cudaEventCreateWithFlags(&evFork, cudaEventDisableTiming);
      cudaEventCreateWithFlags(&evJoin, cudaEventDisableTiming);
    }
  }

  const int B = 256;
  int NB = CDIV(N, 256);    // <= 256 for N <= 65536

  cudaStream_t sc = 0;      // stream for CSR chain (default if no overlap)
  if (s2){
    cudaEventRecord(evFork, 0);
    cudaStreamWaitEvent(s2, evFork, 0);
    sc = s2;
  }

  // CSR build (dst-sorted) + prepvec on side stream
  cudaMemsetAsync(S.deg, 0, (size_t)N*sizeof(int), sc);
  k_hist<<<CDIV(E,B), B, 0, sc>>>(dst, E, S.deg);
  k_scan1<<<NB, 256, 0, sc>>>(S.deg, S.bsum, N);
  k_scan2<<<1, 256, 0, sc>>>(S.bsum, S.boff, S.rowptr, NB, N);
  k_scan3<<<NB, 256, 0, sc>>>(S.deg, S.boff, S.rowptr, S.cursor, N);
  k_scatter<<<CDIV(E,B), B, 0, sc>>>(src, dst, E, S.cursor, S.esrc);
  k_prepvec<<<8, 256, 0, sc>>>(W3, a3s, a3d, S.v);

  // Layer-1 GEMM (independent of CSR) on default stream, overlapped
  k_gemm64f<<<CDIV(N,128), 256>>>(x, W1, a1s, a1d, S.xw, S.as, S.ad, N, 128);

  if (s2){
    cudaEventRecord(evJoin, s2);
    cudaStreamWaitEvent(0, evJoin, 0);
  }

  // Layer 1 aggregation
  k_aggr8<<<(unsigned)CDIV((long long)N*32,B), B>>>(S.rowptr, S.esrc, S.as, S.ad, S.xw, b1,
                                                    S.h0, N, nullptr, nullptr, nullptr);

  // Layer 2 (aggr fuses layer-3 logit dots)
  k_gemm64f<<<CDIV(N,128), 256>>>(S.h0, W2, a2s, a2d, S.xw, S.as, S.ad, N, 64);
  k_aggr8<<<(unsigned)CDIV((long long)N*32,B), B>>>(S.rowptr, S.esrc, S.as, S.ad, S.xw, b2,
                                                    S.h1, N, S.v, S.as3, S.ad3);

  // Layer 3 (linearity): aggregate 64-dim, project last (fused bias/relu/softmax)
  k_aggr64<<<(unsigned)CDIV((long long)N*32,B), B>>>(S.rowptr, S.esrc, S.as3, S.ad3, S.h1, S.xw, N);
  k_gemm242f<<<CDIV(N,16), 242>>>(S.xw, W3, b3, (float*)d_out, N);
}